// round 8
// baseline (speedup 1.0000x reference)
#include <cuda_runtime.h>
#include <math.h>
#include <stdint.h>

// ---------------- problem constants ----------------
#define IMW   256
#define HWIMG 65536          // 256*256
#define BDIM  2
#define CDIM  96
#define C6    576            // 6*DIM
#define C2    192            // 2*DIM
#define CHID  255            // hidden_features
#define CHID2 510            // 2*hidden
#define HEADS 4
#define CH    48             // channels per head (192/4)
#define NF    33             // rfft bins of 64

// ---------------- scratch (static device memory; allocation-free) ----------------
__device__ float g_h1 [(size_t)BDIM * C6    * HWIMG];
__device__ float g_att[(size_t)BDIM * C2    * HWIMG];
__device__ float g_x1 [(size_t)BDIM * CDIM  * HWIMG];
__device__ float g_f1 [(size_t)BDIM * CHID2 * HWIMG];
__device__ float g_g  [(size_t)BDIM * CHID  * HWIMG];
__device__ float g_inv[(size_t)BDIM * HWIMG];          // per-pixel 1/sqrt(var+eps)
__device__ uint32_t g_dft[64 * 72];                    // twiddle matrix, tf32 bits

__device__ __forceinline__ uint32_t f2tf(float f) {
    uint32_t u;
    asm("cvt.rna.tf32.f32 %0, %1;" : "=r"(u) : "f"(f));
    return u;
}

__device__ __forceinline__ void mma_tf32(float* d, uint32_t a0, uint32_t a1,
                                         uint32_t a2, uint32_t a3,
                                         uint32_t b0, uint32_t b1) {
    asm volatile(
        "mma.sync.aligned.m16n8k8.row.col.f32.tf32.tf32.f32 "
        "{%0,%1,%2,%3}, {%4,%5,%6,%7}, {%8,%9}, {%0,%1,%2,%3};\n"
        : "+f"(d[0]), "+f"(d[1]), "+f"(d[2]), "+f"(d[3])
        : "r"(a0), "r"(a1), "r"(a2), "r"(a3), "r"(b0), "r"(b1));
}

// ---------------- twiddle init ----------------
__global__ void dft_init_kernel() {
    int i = blockIdx.x * 256 + threadIdx.x;
    if (i >= 64 * 72) return;
    int n = i / 72, col = i % 72, f = col >> 1;
    float v = 0.f;
    if (col < 66) {
        float ang = 6.2831853071795864f * (float)((f * n) & 63) / 64.f;
        v = (col & 1) ? -sinf(ang) : cosf(ang);
    }
    g_dft[i] = f2tf(v);
}

// ---------------- LN scale only: inv[pix] = rsqrt(var_c + eps) ----------------
__global__ void ln_scale_kernel(const float* __restrict__ x, float* __restrict__ inv) {
    int pix = blockIdx.x * 256 + threadIdx.x;
    int b   = blockIdx.y;
    const float* xb = x + (size_t)b * CDIM * HWIMG + pix;
    float s = 0.f, s2 = 0.f;
    #pragma unroll 8
    for (int c = 0; c < CDIM; c++) {
        float v = xb[(size_t)c * HWIMG];
        s += v; s2 += v * v;
    }
    float mean = s * (1.0f / CDIM);
    float var  = s2 * (1.0f / CDIM) - mean * mean;
    inv[(size_t)b * HWIMG + pix] = rsqrtf(var + 1e-5f);
}

// ---------------- tf32 tensor-core conv1x1 GEMM with optional LN fusion ----------------
#define GBM 128
#define GBN 128
#define GBK 32
#define GPAD 8

template<bool RESID>
__global__ void __launch_bounds__(256) gemm_tf32_kernel(
        const float* __restrict__ A, const float* __restrict__ X,
        const float* __restrict__ R, const float* __restrict__ nw,
        const float* __restrict__ cs, float* __restrict__ Y, int M, int K) {
    __shared__ uint32_t As[GBK][GBM + GPAD];
    __shared__ uint32_t Bs[GBK][GBN + GPAD];

    int tid  = threadIdx.x;
    int warp = tid >> 5, lane = tid & 31;
    int g    = lane >> 2, tg = lane & 3;
    int wm   = (warp & 1) * 64;
    int wn   = (warp >> 1) * 32;

    int bn = blockIdx.x * GBN;
    int bm = blockIdx.y * GBM;
    int b  = blockIdx.z;
    const float* Xb = X + (size_t)b * K * HWIMG + bn;

    float acc[4][4][4];
    #pragma unroll
    for (int mt = 0; mt < 4; mt++)
        #pragma unroll
        for (int nt = 0; nt < 4; nt++)
            #pragma unroll
            for (int i = 0; i < 4; i++) acc[mt][nt][i] = 0.f;

    int xk = tid >> 3;
    int xc = (tid & 7) * 4;

    for (int k0 = 0; k0 < K; k0 += GBK) {
        #pragma unroll
        for (int i = 0; i < 16; i++) {
            int lin = tid + i * 256;
            int m = lin & 127, k = lin >> 7;
            int gm = bm + m, gk = k0 + k;
            float v = (gm < M && gk < K) ? A[(size_t)gm * K + gk] : 0.f;
            if (nw && gk < K) v *= nw[gk];
            As[k][m] = f2tf(v);
        }
        {
            bool kok = (k0 + xk) < K;
            const float* p = Xb + (size_t)(k0 + xk) * HWIMG + xc;
            #pragma unroll
            for (int j = 0; j < 4; j++) {
                float4 v = kok ? *(const float4*)(p + j * 32)
                               : make_float4(0.f, 0.f, 0.f, 0.f);
                int c = xc + j * 32;
                Bs[xk][c + 0] = f2tf(v.x);
                Bs[xk][c + 1] = f2tf(v.y);
                Bs[xk][c + 2] = f2tf(v.z);
                Bs[xk][c + 3] = f2tf(v.w);
            }
        }
        __syncthreads();

        #pragma unroll
        for (int ks = 0; ks < 4; ks++) {
            int kb = ks * 8;
            uint32_t af[4][4], bf[4][2];
            #pragma unroll
            for (int mt = 0; mt < 4; mt++) {
                int m0 = wm + mt * 16;
                af[mt][0] = As[kb + tg    ][m0 + g    ];
                af[mt][1] = As[kb + tg    ][m0 + g + 8];
                af[mt][2] = As[kb + tg + 4][m0 + g    ];
                af[mt][3] = As[kb + tg + 4][m0 + g + 8];
            }
            #pragma unroll
            for (int nt = 0; nt < 4; nt++) {
                int n0 = wn + nt * 8;
                bf[nt][0] = Bs[kb + tg    ][n0 + g];
                bf[nt][1] = Bs[kb + tg + 4][n0 + g];
            }
            #pragma unroll
            for (int mt = 0; mt < 4; mt++)
                #pragma unroll
                for (int nt = 0; nt < 4; nt++)
                    mma_tf32(acc[mt][nt], af[mt][0], af[mt][1], af[mt][2], af[mt][3],
                             bf[nt][0], bf[nt][1]);
        }
        __syncthreads();
    }

    #pragma unroll
    for (int nt = 0; nt < 4; nt++) {
        int n = bn + wn + nt * 8 + 2 * tg;
        float2 sc = make_float2(1.f, 1.f);
        if (cs) sc = *(const float2*)(cs + (size_t)b * HWIMG + n);
        #pragma unroll
        for (int mt = 0; mt < 4; mt++) {
            int m0 = bm + wm + mt * 16 + g;
            int m1 = m0 + 8;
            if (m0 < M) {
                size_t off = ((size_t)b * M + m0) * HWIMG + n;
                float2 o = make_float2(acc[mt][nt][0] * sc.x, acc[mt][nt][1] * sc.y);
                if (RESID) {
                    float2 r = *(const float2*)(R + off);
                    o.x += r.x; o.y += r.y;
                }
                *(float2*)(Y + off) = o;
            }
            if (m1 < M) {
                size_t off = ((size_t)b * M + m1) * HWIMG + n;
                float2 o = make_float2(acc[mt][nt][2] * sc.x, acc[mt][nt][3] * sc.y);
                if (RESID) {
                    float2 r = *(const float2*)(R + off);
                    o.x += r.x; o.y += r.y;
                }
                *(float2*)(Y + off) = o;
            }
        }
    }
}

// ---------------- fused FFN dwconv + gelu gate (float4 tile loads, pitch 76) ----------------
#define DWP 76

__device__ __forceinline__ void dw_load_tile4(const float* __restrict__ ip,
                                              float* __restrict__ tile,
                                              int y0, int x0, int tid) {
    // tile col m <-> gx = x0 - 4 + m, m in [0,72)
    for (int i = tid; i < 34 * 18; i += 256) {
        int r = i / 18, k = i - r * 18;
        int gy = y0 - 1 + r;
        int gx = x0 - 4 + k * 4;
        float4 v = make_float4(0.f, 0.f, 0.f, 0.f);
        if (gy >= 0 && gy < 256 && gx >= 0 && gx < 256)
            v = *(const float4*)(ip + gy * IMW + gx);
        *(float4*)&tile[r * DWP + k * 4] = v;
    }
}

__device__ __forceinline__ void dw_compute8(const float* __restrict__ tile,
                                            const float* __restrict__ wr,
                                            int row, int col0, float* o) {
    float r0[10], r1[10], r2[10];
    const float* t0 = tile + row * DWP + col0 + 3;   // gx = x0 + col0 - 1
    #pragma unroll
    for (int j = 0; j < 10; j++) {
        r0[j] = t0[j];
        r1[j] = t0[DWP + j];
        r2[j] = t0[2 * DWP + j];
    }
    #pragma unroll
    for (int j = 0; j < 8; j++) {
        o[j] = r0[j] * wr[0] + r0[j+1] * wr[1] + r0[j+2] * wr[2]
             + r1[j] * wr[3] + r1[j+1] * wr[4] + r1[j+2] * wr[5]
             + r2[j] * wr[6] + r2[j+1] * wr[7] + r2[j+2] * wr[8];
    }
}

__global__ void __launch_bounds__(256) dwgate_kernel(
        const float* __restrict__ in, const float* __restrict__ w,
        float* __restrict__ gout) {
    __shared__ float tile1[34 * DWP];
    __shared__ float tile2[34 * DWP];
    int tid = threadIdx.x;
    int t   = blockIdx.x;            // 0..31 : 8 y-tiles x 4 x-tiles
    int c   = blockIdx.y, b = blockIdx.z;
    int y0  = (t >> 2) * 32, x0 = (t & 3) * 64;

    const float* ip1 = in + ((size_t)b * CHID2 + c) * HWIMG;
    const float* ip2 = in + ((size_t)b * CHID2 + CHID + c) * HWIMG;
    dw_load_tile4(ip1, tile1, y0, x0, tid);
    dw_load_tile4(ip2, tile2, y0, x0, tid);

    float wr1[9], wr2[9];
    #pragma unroll
    for (int j = 0; j < 9; j++) {
        wr1[j] = w[c * 9 + j];
        wr2[j] = w[(CHID + c) * 9 + j];
    }
    __syncthreads();

    int row = tid >> 3, col0 = (tid & 7) * 8;
    float v1[8], v2[8];
    dw_compute8(tile1, wr1, row, col0, v1);
    dw_compute8(tile2, wr2, row, col0, v2);

    float o[8];
    #pragma unroll
    for (int j = 0; j < 8; j++) {
        float ge = 0.5f * v1[j] * (1.f + erff(v1[j] * 0.70710678118654752f));
        o[j] = ge * v2[j];
    }
    float* op = gout + ((size_t)b * CHID + c) * HWIMG + (y0 + row) * IMW + x0 + col0;
    *(float4*)op       = make_float4(o[0], o[1], o[2], o[3]);
    *(float4*)(op + 4) = make_float4(o[4], o[5], o[6], o[7]);
}

// ---------------- windowed FFT attention with FUSED depthwise conv ----------------
// smem floats (unchanged footprint, 2 CTAs/SM):
//   ASX: sxT 64x152 (tf32) -> later PT 72x56          [9728]
//   AD : D   64x72  (tf32)                            [4608]
//   AQF: QF 144x68 fp32; first overlaid by dw staging [9792]
//   AAT: at 33x33 float2                              [2178]
//   ANR: nrm 33
#define ASX 0
#define AD  9728
#define AQF 14336
#define AAT 24128
#define ANR 26306
#define ATTN_SMEM_FLOATS 26339

__global__ void __launch_bounds__(256, 2) attn_kernel(
        const float* __restrict__ h1, const float* __restrict__ dww,
        const float* __restrict__ temp, float* __restrict__ outp) {
    extern __shared__ float sm[];
    uint32_t* sxT = (uint32_t*)(sm + ASX);
    uint32_t* Ds  = (uint32_t*)(sm + AD);
    float*    QF  = sm + AQF;
    float2*   at2 = (float2*)(sm + AAT);
    float*    nrm = sm + ANR;

    int tid  = threadIdx.x;
    int warp = tid >> 5, lane = tid & 31;
    int g    = lane >> 2, tg = lane & 3;
    int wy   = blockIdx.x >> 5, wx = blockIdx.x & 31;
    int head = blockIdx.y, b = blockIdx.z;

    for (int i = tid; i < 64 * 72; i += 256) Ds[i] = g_dft[i];

    // ---- fused dwconv3x3 + tf32 window load: 144 channel-windows in 9 chunks of 16 ----
    // staging overlays QF region (16 ch x 10 rows x pitch 12 = 1920 floats)
    float* stage = QF;
    int py0 = wy * 8, px0w = wx * 8;
    #pragma unroll 1
    for (int chunk = 0; chunk < 9; chunk++) {
        __syncthreads();   // stage reuse (first iter: also covers Ds for nobody yet)
        for (int i = tid; i < 1600; i += 256) {
            int ch = i / 100, e = i - ch * 100;
            int r = e / 10, col = e - r * 10;
            int gidx = chunk * 16 + ch;
            int t = gidx / 48, c = gidx - t * 48;
            const float* p = h1 + ((size_t)b * C6 + t * C2 + head * CH + c) * HWIMG;
            int gy = py0 - 1 + r, gx = px0w - 1 + col;
            float v = 0.f;
            if (gy >= 0 && gy < 256 && gx >= 0 && gx < 256)
                v = p[gy * IMW + gx];
            stage[ch * 120 + r * 12 + col] = v;
        }
        __syncthreads();
        {
            int ch = tid >> 4, n0 = (tid & 15) * 4;
            int gidx = chunk * 16 + ch;
            int t = gidx / 48, c = gidx - t * 48;
            int gc = t * C2 + head * CH + c;
            int py = n0 >> 3, pxx = n0 & 7;
            const float* st = stage + ch * 120 + py * 12 + pxx;
            float wr[9];
            #pragma unroll
            for (int j = 0; j < 9; j++) wr[j] = dww[gc * 9 + j];
            float rr[3][6];
            #pragma unroll
            for (int dy = 0; dy < 3; dy++)
                #pragma unroll
                for (int dx = 0; dx < 6; dx++) rr[dy][dx] = st[dy * 12 + dx];
            #pragma unroll
            for (int jj = 0; jj < 4; jj++) {
                float s = rr[0][jj] * wr[0] + rr[0][jj+1] * wr[1] + rr[0][jj+2] * wr[2]
                        + rr[1][jj] * wr[3] + rr[1][jj+1] * wr[4] + rr[1][jj+2] * wr[5]
                        + rr[2][jj] * wr[6] + rr[2][jj+1] * wr[7] + rr[2][jj+2] * wr[8];
                sxT[(n0 + jj) * 152 + gidx] = f2tf(s);
            }
        }
    }
    __syncthreads();

    // ---- DFT via MMA: QF(144x66) = Sx(144x64) * D(64x66) ----
    for (int mt = warp; mt < 9; mt += 8) {
        int m0 = mt * 16;
        float acc[9][4];
        #pragma unroll
        for (int nt = 0; nt < 9; nt++)
            acc[nt][0] = acc[nt][1] = acc[nt][2] = acc[nt][3] = 0.f;
        #pragma unroll
        for (int kc = 0; kc < 8; kc++) {
            int kb = kc * 8;
            uint32_t a0 = sxT[(kb + tg)     * 152 + m0 + g];
            uint32_t a1 = sxT[(kb + tg)     * 152 + m0 + g + 8];
            uint32_t a2 = sxT[(kb + tg + 4) * 152 + m0 + g];
            uint32_t a3 = sxT[(kb + tg + 4) * 152 + m0 + g + 8];
            #pragma unroll
            for (int nt = 0; nt < 9; nt++) {
                uint32_t b0 = Ds[(kb + tg)     * 72 + nt * 8 + g];
                uint32_t b1 = Ds[(kb + tg + 4) * 72 + nt * 8 + g];
                mma_tf32(acc[nt], a0, a1, a2, a3, b0, b1);
            }
        }
        #pragma unroll
        for (int nt = 0; nt < 9; nt++) {
            int col = nt * 8 + 2 * tg;
            if (col < 66) {
                *(float2*)&QF[(m0 + g)     * 68 + col] = make_float2(acc[nt][0], acc[nt][1]);
                *(float2*)&QF[(m0 + g + 8) * 68 + col] = make_float2(acc[nt][2], acc[nt][3]);
            }
        }
    }
    __syncthreads();

    // ---- gram ----
    float tv = temp[head];
    const float2* qf2 = (const float2*)QF;
    for (int e = tid; e < 17 * 17; e += 256) {
        int ft = e / 17, gt = e - ft * 17;
        int f0 = ft * 2, g0 = gt * 2;
        int f1 = (f0 + 1 < NF) ? f0 + 1 : f0;
        int g1 = (g0 + 1 < NF) ? g0 + 1 : g0;
        float2 a00 = {0,0}, a01 = {0,0}, a10 = {0,0}, a11 = {0,0};
        #pragma unroll 4
        for (int c = 0; c < CH; c++) {
            float2 q0 = qf2[c * 34 + f0], q1 = qf2[c * 34 + f1];
            float2 k0 = qf2[(CH + c) * 34 + g0], k1 = qf2[(CH + c) * 34 + g1];
            a00.x += q0.x*k0.x - q0.y*k0.y; a00.y += q0.x*k0.y + q0.y*k0.x;
            a01.x += q0.x*k1.x - q0.y*k1.y; a01.y += q0.x*k1.y + q0.y*k1.x;
            a10.x += q1.x*k0.x - q1.y*k0.y; a10.y += q1.x*k0.y + q1.y*k0.x;
            a11.x += q1.x*k1.x - q1.y*k1.y; a11.y += q1.x*k1.y + q1.y*k1.x;
        }
        at2[f0 * NF + g0] = make_float2(a00.x * tv, a00.y * tv);
        if (g0 + 1 < NF) at2[f0 * NF + g0 + 1] = make_float2(a01.x * tv, a01.y * tv);
        if (f0 + 1 < NF) {
            at2[(f0 + 1) * NF + g0] = make_float2(a10.x * tv, a10.y * tv);
            if (g0 + 1 < NF) at2[(f0 + 1) * NF + g0 + 1] = make_float2(a11.x * tv, a11.y * tv);
        }
    }
    __syncthreads();

    uint32_t* PT = sxT;
    if (tid < NF) {
        float s = 0.f;
        #pragma unroll
        for (int gg = 0; gg < NF; gg++) {
            float2 a = at2[tid * NF + gg];
            s += a.x * a.x + a.y * a.y;
        }
        nrm[tid] = rsqrtf(s);
    }
    for (int i = tid; i < 6 * 56; i += 256) PT[66 * 56 + i] = 0u;
    __syncthreads();

    // ---- apply ----
    if (tid < 204) {
        int cg = tid % 12, fg = tid / 12;
        int c0 = cg * 4, f0 = fg * 2;
        bool has1 = (f0 + 1) < NF;
        int f1 = has1 ? f0 + 1 : f0;
        float2 acc0[4] = {{0,0},{0,0},{0,0},{0,0}};
        float2 acc1[4] = {{0,0},{0,0},{0,0},{0,0}};
        #pragma unroll 3
        for (int gg = 0; gg < NF; gg++) {
            float2 a0 = at2[f0 * NF + gg], a1 = at2[f1 * NF + gg];
            #pragma unroll
            for (int j = 0; j < 4; j++) {
                float2 v = qf2[(2 * CH + c0 + j) * 34 + gg];
                acc0[j].x += a0.x*v.x - a0.y*v.y; acc0[j].y += a0.x*v.y + a0.y*v.x;
                acc1[j].x += a1.x*v.x - a1.y*v.y; acc1[j].y += a1.x*v.y + a1.y*v.x;
            }
        }
        float s0 = nrm[f0] * ((f0 == 0 || f0 == 32) ? 1.f : 2.f) * (1.f / 64.f);
        float s1 = nrm[f1] * 2.f * (1.f / 64.f);
        #pragma unroll
        for (int j = 0; j < 4; j++) {
            PT[(2 * f0)     * 56 + c0 + j] = f2tf(acc0[j].x * s0);
            PT[(2 * f0 + 1) * 56 + c0 + j] = f2tf(acc0[j].y * s0);
            if (has1) {
                PT[(2 * f1)     * 56 + c0 + j] = f2tf(acc1[j].x * s1);
                PT[(2 * f1 + 1) * 56 + c0 + j] = f2tf(acc1[j].y * s1);
            }
        }
    }
    __syncthreads();

    // ---- irDFT via MMA ----
    float* outBase = outp + ((size_t)b * C2 + head * CH) * HWIMG
                   + (size_t)(wy * 8) * IMW + wx * 8;
    for (int t = warp; t < 24; t += 8) {
        int mt = t / 8, nt = t % 8;
        int m0 = mt * 16, n0 = nt * 8;
        float acc[4] = {0.f, 0.f, 0.f, 0.f};
        #pragma unroll
        for (int kc = 0; kc < 9; kc++) {
            int kb = kc * 8;
            uint32_t a0 = PT[(kb + tg)     * 56 + m0 + g];
            uint32_t a1 = PT[(kb + tg)     * 56 + m0 + g + 8];
            uint32_t a2 = PT[(kb + tg + 4) * 56 + m0 + g];
            uint32_t a3 = PT[(kb + tg + 4) * 56 + m0 + g + 4 + 4];
            uint32_t b0 = Ds[(n0 + g) * 72 + kb + tg];
            uint32_t b1 = Ds[(n0 + g) * 72 + kb + tg + 4];
            mma_tf32(acc, a0, a1, a2, a3, b0, b1);
        }
        int c = m0 + g;
        *(float2*)&outBase[(size_t)c       * HWIMG + nt * IMW + 2 * tg] =
            make_float2(acc[0], acc[1]);
        *(float2*)&outBase[(size_t)(c + 8) * HWIMG + nt * IMW + 2 * tg] =
            make_float2(acc[2], acc[3]);
    }
}

// ---------------- launch ----------------
extern "C" void kernel_launch(void* const* d_in, const int* in_sizes, int n_in,
                              void* d_out, int out_size) {
    const float* x      = (const float*)d_in[0];
    const float* w_hid  = (const float*)d_in[1];
    const float* w_hdw  = (const float*)d_in[2];
    const float* w_proj = (const float*)d_in[3];
    const float* temp   = (const float*)d_in[4];
    const float* n1w    = (const float*)d_in[5];
    const float* n2w    = (const float*)d_in[6];
    const float* w_fin  = (const float*)d_in[7];
    const float* w_fdw  = (const float*)d_in[8];
    const float* w_fout = (const float*)d_in[9];
    float* out = (float*)d_out;

    float *h1, *att, *x1, *f1, *gg, *inv;
    cudaGetSymbolAddress((void**)&h1,  g_h1);
    cudaGetSymbolAddress((void**)&att, g_att);
    cudaGetSymbolAddress((void**)&x1,  g_x1);
    cudaGetSymbolAddress((void**)&f1,  g_f1);
    cudaGetSymbolAddress((void**)&gg,  g_g);
    cudaGetSymbolAddress((void**)&inv, g_inv);

    cudaFuncSetAttribute(attn_kernel, cudaFuncAttributeMaxDynamicSharedMemorySize,
                         ATTN_SMEM_FLOATS * 4);

    // 0) twiddle matrix init
    dft_init_kernel<<<18, 256>>>();
    // 1) LN1 scale
    ln_scale_kernel<<<dim3(256, BDIM), 256>>>(x, inv);
    // 2) to_hidden 1x1 (96 -> 576), LN fused
    gemm_tf32_kernel<false><<<dim3(512, 5, BDIM), 256>>>(w_hid, x, nullptr, n1w, inv, h1, C6, CDIM);
    // 3) windowed FFT attention with FUSED dwconv3x3
    attn_kernel<<<dim3(1024, HEADS, BDIM), 256, ATTN_SMEM_FLOATS * 4>>>(h1, w_hdw, temp, att);
    // 4) project_out 1x1 (192 -> 96) + residual x
    gemm_tf32_kernel<true><<<dim3(512, 1, BDIM), 256>>>(w_proj, att, x, nullptr, nullptr, x1, CDIM, C2);
    // 5) LN2 scale
    ln_scale_kernel<<<dim3(256, BDIM), 256>>>(x1, inv);
    // 6) ffn in 1x1 (96 -> 510), LN fused
    gemm_tf32_kernel<false><<<dim3(512, 4, BDIM), 256>>>(w_fin, x1, nullptr, n2w, inv, f1, CHID2, CDIM);
    // 7) fused dwconv 3x3 + gelu gate (tiled, float4 loads)
    dwgate_kernel<<<dim3(32, CHID, BDIM), 256>>>(f1, w_fdw, gg);
    // 8) ffn out 1x1 (255 -> 96) + residual x1 -> d_out
    gemm_tf32_kernel<true><<<dim3(512, 1, BDIM), 256>>>(w_fout, gg, x1, nullptr, nullptr, out, CDIM, CHID);
}

// round 9
// speedup vs baseline: 1.3721x; 1.3721x over previous
#include <cuda_runtime.h>
#include <math.h>
#include <stdint.h>

// ---------------- problem constants ----------------
#define IMW   256
#define HWIMG 65536          // 256*256
#define BDIM  2
#define CDIM  96
#define C6    576            // 6*DIM
#define C2    192            // 2*DIM
#define CHID  255            // hidden_features
#define CHID2 510            // 2*hidden
#define HEADS 4
#define CH    48             // channels per head
#define NF    33             // rfft bins of 64

// ---------------- scratch ----------------
__device__ float g_h1 [(size_t)BDIM * C6    * HWIMG];
__device__ float g_h2 [(size_t)BDIM * C6    * HWIMG];
__device__ float g_att[(size_t)BDIM * C2    * HWIMG];
__device__ float g_x1 [(size_t)BDIM * CDIM  * HWIMG];
__device__ float g_f1 [(size_t)BDIM * CHID2 * HWIMG];
__device__ float g_g  [(size_t)BDIM * CHID  * HWIMG];
__device__ float g_inv[(size_t)BDIM * HWIMG];
__device__ uint32_t g_dft[64 * 84];   // Ds[n][2f]=cos, [2f+1]=-sin, cols>=66 zero

__device__ __forceinline__ uint32_t f2tf(float f) {
    uint32_t u;
    asm("cvt.rna.tf32.f32 %0, %1;" : "=r"(u) : "f"(f));
    return u;
}
__device__ __forceinline__ uint32_t fneg(uint32_t u) { return u ^ 0x80000000u; }

__device__ __forceinline__ void mma_tf32(float* d, uint32_t a0, uint32_t a1,
                                         uint32_t a2, uint32_t a3,
                                         uint32_t b0, uint32_t b1) {
    asm volatile(
        "mma.sync.aligned.m16n8k8.row.col.f32.tf32.tf32.f32 "
        "{%0,%1,%2,%3}, {%4,%5,%6,%7}, {%8,%9}, {%0,%1,%2,%3};\n"
        : "+f"(d[0]), "+f"(d[1]), "+f"(d[2]), "+f"(d[3])
        : "r"(a0), "r"(a1), "r"(a2), "r"(a3), "r"(b0), "r"(b1));
}

// ---------------- twiddle init ----------------
__global__ void dft_init_kernel() {
    int i = blockIdx.x * 256 + threadIdx.x;
    if (i >= 64 * 84) return;
    int n = i / 84, col = i % 84, f = col >> 1;
    float v = 0.f;
    if (col < 66) {
        float ang = 6.2831853071795864f * (float)((f * n) & 63) / 64.f;
        v = (col & 1) ? -sinf(ang) : cosf(ang);
    }
    g_dft[i] = f2tf(v);
}

// ---------------- LN scale only ----------------
__global__ void ln_scale_kernel(const float* __restrict__ x, float* __restrict__ inv) {
    int pix = blockIdx.x * 256 + threadIdx.x;
    int b   = blockIdx.y;
    const float* xb = x + (size_t)b * CDIM * HWIMG + pix;
    float s = 0.f, s2 = 0.f;
    #pragma unroll 8
    for (int c = 0; c < CDIM; c++) {
        float v = xb[(size_t)c * HWIMG];
        s += v; s2 += v * v;
    }
    float mean = s * (1.0f / CDIM);
    float var  = s2 * (1.0f / CDIM) - mean * mean;
    inv[(size_t)b * HWIMG + pix] = rsqrtf(var + 1e-5f);
}

// ---------------- tf32 conv1x1 GEMM (proven R3 version + LN fusion) ----------------
#define GBM 128
#define GBN 128
#define GBK 32
#define GPAD 8

template<bool RESID>
__global__ void __launch_bounds__(256) gemm_tf32_kernel(
        const float* __restrict__ A, const float* __restrict__ X,
        const float* __restrict__ R, const float* __restrict__ nw,
        const float* __restrict__ cs, float* __restrict__ Y, int M, int K) {
    __shared__ uint32_t As[GBK][GBM + GPAD];
    __shared__ uint32_t Bs[GBK][GBN + GPAD];

    int tid  = threadIdx.x;
    int warp = tid >> 5, lane = tid & 31;
    int g    = lane >> 2, tg = lane & 3;
    int wm   = (warp & 1) * 64;
    int wn   = (warp >> 1) * 32;

    int bn = blockIdx.x * GBN;
    int bm = blockIdx.y * GBM;
    int b  = blockIdx.z;
    const float* Xb = X + (size_t)b * K * HWIMG + bn;

    float acc[4][4][4];
    #pragma unroll
    for (int mt = 0; mt < 4; mt++)
        #pragma unroll
        for (int nt = 0; nt < 4; nt++)
            #pragma unroll
            for (int i = 0; i < 4; i++) acc[mt][nt][i] = 0.f;

    int xk = tid >> 3;
    int xc = (tid & 7) * 4;

    for (int k0 = 0; k0 < K; k0 += GBK) {
        #pragma unroll
        for (int i = 0; i < 16; i++) {
            int lin = tid + i * 256;
            int m = lin & 127, k = lin >> 7;
            int gm = bm + m, gk = k0 + k;
            float v = (gm < M && gk < K) ? A[(size_t)gm * K + gk] : 0.f;
            if (nw && gk < K) v *= nw[gk];
            As[k][m] = f2tf(v);
        }
        {
            bool kok = (k0 + xk) < K;
            const float* p = Xb + (size_t)(k0 + xk) * HWIMG + xc;
            #pragma unroll
            for (int j = 0; j < 4; j++) {
                float4 v = kok ? *(const float4*)(p + j * 32)
                               : make_float4(0.f, 0.f, 0.f, 0.f);
                int c = xc + j * 32;
                Bs[xk][c + 0] = f2tf(v.x);
                Bs[xk][c + 1] = f2tf(v.y);
                Bs[xk][c + 2] = f2tf(v.z);
                Bs[xk][c + 3] = f2tf(v.w);
            }
        }
        __syncthreads();

        #pragma unroll
        for (int ks = 0; ks < 4; ks++) {
            int kb = ks * 8;
            uint32_t af[4][4], bf[4][2];
            #pragma unroll
            for (int mt = 0; mt < 4; mt++) {
                int m0 = wm + mt * 16;
                af[mt][0] = As[kb + tg    ][m0 + g    ];
                af[mt][1] = As[kb + tg    ][m0 + g + 8];
                af[mt][2] = As[kb + tg + 4][m0 + g    ];
                af[mt][3] = As[kb + tg + 4][m0 + g + 8];
            }
            #pragma unroll
            for (int nt = 0; nt < 4; nt++) {
                int n0 = wn + nt * 8;
                bf[nt][0] = Bs[kb + tg    ][n0 + g];
                bf[nt][1] = Bs[kb + tg + 4][n0 + g];
            }
            #pragma unroll
            for (int mt = 0; mt < 4; mt++)
                #pragma unroll
                for (int nt = 0; nt < 4; nt++)
                    mma_tf32(acc[mt][nt], af[mt][0], af[mt][1], af[mt][2], af[mt][3],
                             bf[nt][0], bf[nt][1]);
        }
        __syncthreads();
    }

    #pragma unroll
    for (int nt = 0; nt < 4; nt++) {
        int n = bn + wn + nt * 8 + 2 * tg;
        float2 sc = make_float2(1.f, 1.f);
        if (cs) sc = *(const float2*)(cs + (size_t)b * HWIMG + n);
        #pragma unroll
        for (int mt = 0; mt < 4; mt++) {
            int m0 = bm + wm + mt * 16 + g;
            int m1 = m0 + 8;
            if (m0 < M) {
                size_t off = ((size_t)b * M + m0) * HWIMG + n;
                float2 o = make_float2(acc[mt][nt][0] * sc.x, acc[mt][nt][1] * sc.y);
                if (RESID) {
                    float2 r = *(const float2*)(R + off);
                    o.x += r.x; o.y += r.y;
                }
                *(float2*)(Y + off) = o;
            }
            if (m1 < M) {
                size_t off = ((size_t)b * M + m1) * HWIMG + n;
                float2 o = make_float2(acc[mt][nt][2] * sc.x, acc[mt][nt][3] * sc.y);
                if (RESID) {
                    float2 r = *(const float2*)(R + off);
                    o.x += r.x; o.y += r.y;
                }
                *(float2*)(Y + off) = o;
            }
        }
    }
}

// ---------------- tiled depthwise 3x3 (float4 loads, pitch 76) ----------------
#define DWP 76

__device__ __forceinline__ void dw_load_tile4(const float* __restrict__ ip,
                                              float* __restrict__ tile,
                                              int y0, int x0, int tid) {
    for (int i = tid; i < 34 * 18; i += 256) {
        int r = i / 18, k = i - r * 18;
        int gy = y0 - 1 + r;
        int gx = x0 - 4 + k * 4;
        float4 v = make_float4(0.f, 0.f, 0.f, 0.f);
        if (gy >= 0 && gy < 256 && gx >= 0 && gx < 256)
            v = *(const float4*)(ip + gy * IMW + gx);
        *(float4*)&tile[r * DWP + k * 4] = v;
    }
}

__device__ __forceinline__ void dw_compute8(const float* __restrict__ tile,
                                            const float* __restrict__ wr,
                                            int row, int col0, float* o) {
    float r0[10], r1[10], r2[10];
    const float* t0 = tile + row * DWP + col0 + 3;
    #pragma unroll
    for (int j = 0; j < 10; j++) {
        r0[j] = t0[j];
        r1[j] = t0[DWP + j];
        r2[j] = t0[2 * DWP + j];
    }
    #pragma unroll
    for (int j = 0; j < 8; j++) {
        o[j] = r0[j] * wr[0] + r0[j+1] * wr[1] + r0[j+2] * wr[2]
             + r1[j] * wr[3] + r1[j+1] * wr[4] + r1[j+2] * wr[5]
             + r2[j] * wr[6] + r2[j+1] * wr[7] + r2[j+2] * wr[8];
    }
}

__global__ void __launch_bounds__(256) dwconv_kernel(
        const float* __restrict__ in, const float* __restrict__ w,
        float* __restrict__ out, int C) {
    __shared__ float tile[34 * DWP];
    int tid = threadIdx.x;
    int t   = blockIdx.x;
    int c   = blockIdx.y, b = blockIdx.z;
    int y0  = (t >> 2) * 32, x0 = (t & 3) * 64;

    const float* ip = in + ((size_t)b * C + c) * HWIMG;
    dw_load_tile4(ip, tile, y0, x0, tid);
    float wr[9];
    #pragma unroll
    for (int j = 0; j < 9; j++) wr[j] = w[c * 9 + j];
    __syncthreads();

    int row = tid >> 3, col0 = (tid & 7) * 8;
    float o[8];
    dw_compute8(tile, wr, row, col0, o);
    float* op = out + ((size_t)b * C + c) * HWIMG + (y0 + row) * IMW + x0 + col0;
    *(float4*)op       = make_float4(o[0], o[1], o[2], o[3]);
    *(float4*)(op + 4) = make_float4(o[4], o[5], o[6], o[7]);
}

__global__ void __launch_bounds__(256) dwgate_kernel(
        const float* __restrict__ in, const float* __restrict__ w,
        float* __restrict__ gout) {
    __shared__ float tile1[34 * DWP];
    __shared__ float tile2[34 * DWP];
    int tid = threadIdx.x;
    int t   = blockIdx.x;
    int c   = blockIdx.y, b = blockIdx.z;
    int y0  = (t >> 2) * 32, x0 = (t & 3) * 64;

    const float* ip1 = in + ((size_t)b * CHID2 + c) * HWIMG;
    const float* ip2 = in + ((size_t)b * CHID2 + CHID + c) * HWIMG;
    dw_load_tile4(ip1, tile1, y0, x0, tid);
    dw_load_tile4(ip2, tile2, y0, x0, tid);
    float wr1[9], wr2[9];
    #pragma unroll
    for (int j = 0; j < 9; j++) {
        wr1[j] = w[c * 9 + j];
        wr2[j] = w[(CHID + c) * 9 + j];
    }
    __syncthreads();

    int row = tid >> 3, col0 = (tid & 7) * 8;
    float v1[8], v2[8];
    dw_compute8(tile1, wr1, row, col0, v1);
    dw_compute8(tile2, wr2, row, col0, v2);
    float o[8];
    #pragma unroll
    for (int j = 0; j < 8; j++) {
        float ge = 0.5f * v1[j] * (1.f + erff(v1[j] * 0.70710678118654752f));
        o[j] = ge * v2[j];
    }
    float* op = gout + ((size_t)b * CHID + c) * HWIMG + (y0 + row) * IMW + x0 + col0;
    *(float4*)op       = make_float4(o[0], o[1], o[2], o[3]);
    *(float4*)(op + 4) = make_float4(o[4], o[5], o[6], o[7]);
}

// ---------------- windowed FFT attention: ALL contractions on tensor pipe ----------------
// smem floats:
//  Ds   @0      64x84 tf32                          (5376)
//  sxT  @5376   64x152 tf32 [time][channel]         (9728)
//    overlay after DFT: atTr @5376 40x56, atTi @7616 40x56, PT @9856 72x56
//  QKT  @15104  96x84 tf32 [c][fcomp]  (fcomp: 0..39 Re-f, 40..79 Im-f)
//  VT   @23168  80x56 tf32 [gcomp][c]
//  sc   @27648  33+pad
#define SM_DS  0
#define SM_SX  5376
#define SM_ATR 5376
#define SM_ATI 7616
#define SM_PT  9856
#define SM_QKT 15104
#define SM_VT  23168
#define SM_SC  27648
#define ATTN_SMEM_FLOATS 27688

__global__ void __launch_bounds__(256) attn_kernel(
        const float* __restrict__ qkv, const float* __restrict__ temp,
        float* __restrict__ outp) {
    extern __shared__ float sm[];
    uint32_t* Ds  = (uint32_t*)(sm + SM_DS);
    uint32_t* sx  = (uint32_t*)(sm + SM_SX);
    uint32_t* atr = (uint32_t*)(sm + SM_ATR);
    uint32_t* ati = (uint32_t*)(sm + SM_ATI);
    uint32_t* PT  = (uint32_t*)(sm + SM_PT);
    uint32_t* QKT = (uint32_t*)(sm + SM_QKT);
    uint32_t* VT  = (uint32_t*)(sm + SM_VT);
    float*    sc  = sm + SM_SC;

    int tid  = threadIdx.x;
    int warp = tid >> 5, lane = tid & 31;
    int g    = lane >> 2, tg = lane & 3;
    int wy   = blockIdx.x >> 5, wx = blockIdx.x & 31;
    int head = blockIdx.y, b = blockIdx.z;
    float tv = temp[head];

    size_t base = ((size_t)b * C6 + head * CH) * HWIMG + (size_t)(wy * 8) * IMW + wx * 8;

    // ---- phase 1: load twiddles + window ----
    for (int i = tid; i < 64 * 84; i += 256) Ds[i] = g_dft[i];
    for (int i = tid; i < 3 * CH * 64; i += 256) {
        int t = i / 3072, rem = i - t * 3072;
        int c = rem >> 6, n = rem & 63;
        float v = qkv[base + (size_t)(t * C2 + c) * HWIMG + (n >> 3) * IMW + (n & 7)];
        sx[n * 152 + t * CH + c] = f2tf(v);
    }
    __syncthreads();

    // ---- phase 2: DFT  QFT[fcomp][c] = sum_t E[fcomp][t] * X[c][t] ----
    // E[fcomp][t] = Ds[t][2*fcomp] (fcomp<40) or Ds[t][2*(fcomp-40)+1]
    for (int t8 = warp; t8 < 90; t8 += 8) {
        int mt = t8 / 18, nt = t8 % 18;
        int m0 = mt * 16, n0 = nt * 8;
        int mA = m0 + g, mB = mA + 8;
        int colA = (mA < 40) ? 2 * mA : 2 * (mA - 40) + 1;
        int colB = (mB < 40) ? 2 * mB : 2 * (mB - 40) + 1;
        float acc[4] = {0.f, 0.f, 0.f, 0.f};
        #pragma unroll
        for (int kc = 0; kc < 8; kc++) {
            int kb = kc * 8;
            uint32_t a0 = Ds[(kb + tg)     * 84 + colA];
            uint32_t a1 = Ds[(kb + tg)     * 84 + colB];
            uint32_t a2 = Ds[(kb + tg + 4) * 84 + colA];
            uint32_t a3 = Ds[(kb + tg + 4) * 84 + colB];
            uint32_t b0 = sx[(kb + tg)     * 152 + n0 + g];
            uint32_t b1 = sx[(kb + tg + 4) * 152 + n0 + g];
            mma_tf32(acc, a0, a1, a2, a3, b0, b1);
        }
        int c0 = n0 + 2 * tg;
        if (n0 < 96) {   // Q,K -> transposed [c][fcomp]
            QKT[c0 * 84 + mA]       = f2tf(acc[0]);
            QKT[(c0 + 1) * 84 + mA] = f2tf(acc[1]);
            QKT[c0 * 84 + mB]       = f2tf(acc[2]);
            QKT[(c0 + 1) * 84 + mB] = f2tf(acc[3]);
        } else {         // V -> direct [gcomp][c]
            int cv = c0 - 96;
            VT[mA * 56 + cv]     = f2tf(acc[0]);
            VT[mA * 56 + cv + 1] = f2tf(acc[1]);
            VT[mB * 56 + cv]     = f2tf(acc[2]);
            VT[mB * 56 + cv + 1] = f2tf(acc[3]);
        }
    }
    __syncthreads();

    // ---- phase 3: gram  at[f][g] = sum_c QF[c][f]*KF[c][g] -> store atT[g][f] ----
    for (int t8 = warp; t8 < 15; t8 += 8) {
        int mt = t8 / 5, nt = t8 % 5;
        int m0 = mt * 16, n0 = nt * 8;
        int fA = m0 + g, fB = fA + 8;
        int ciA = 40 + ((fA < 40) ? fA : 0);   // clamp (garbage rows ignored)
        int ciB = 40 + ((fB < 40) ? fB : 0);
        float aR[4] = {0,0,0,0}, aI[4] = {0,0,0,0};
        #pragma unroll
        for (int kc = 0; kc < 6; kc++) {
            int kb = kc * 8;
            uint32_t qr0 = QKT[(kb + tg)     * 84 + fA];
            uint32_t qr1 = QKT[(kb + tg)     * 84 + fB];
            uint32_t qr2 = QKT[(kb + tg + 4) * 84 + fA];
            uint32_t qr3 = QKT[(kb + tg + 4) * 84 + fB];
            uint32_t qi0 = QKT[(kb + tg)     * 84 + ciA];
            uint32_t qi1 = QKT[(kb + tg)     * 84 + ciB];
            uint32_t qi2 = QKT[(kb + tg + 4) * 84 + ciA];
            uint32_t qi3 = QKT[(kb + tg + 4) * 84 + ciB];
            uint32_t kr0 = QKT[(48 + kb + tg)     * 84 + n0 + g];
            uint32_t kr1 = QKT[(48 + kb + tg + 4) * 84 + n0 + g];
            uint32_t ki0 = QKT[(48 + kb + tg)     * 84 + 40 + n0 + g];
            uint32_t ki1 = QKT[(48 + kb + tg + 4) * 84 + 40 + n0 + g];
            mma_tf32(aR, qr0, qr1, qr2, qr3, kr0, kr1);
            mma_tf32(aR, qi0, qi1, qi2, qi3, fneg(ki0), fneg(ki1));
            mma_tf32(aI, qr0, qr1, qr2, qr3, ki0, ki1);
            mma_tf32(aI, qi0, qi1, qi2, qi3, kr0, kr1);
        }
        int gc0 = n0 + 2 * tg, gc1 = gc0 + 1;
        atr[gc0 * 56 + fA] = f2tf(aR[0]);  ati[gc0 * 56 + fA] = f2tf(aI[0]);
        atr[gc1 * 56 + fA] = f2tf(aR[1]);  ati[gc1 * 56 + fA] = f2tf(aI[1]);
        atr[gc0 * 56 + fB] = f2tf(aR[2]);  ati[gc0 * 56 + fB] = f2tf(aI[2]);
        atr[gc1 * 56 + fB] = f2tf(aR[3]);  ati[gc1 * 56 + fB] = f2tf(aI[3]);
    }
    __syncthreads();

    // ---- phase 4: row norms -> scale[f]; zero PT pad rows 66..71 ----
    if (tid < NF) {
        float s = 0.f;
        #pragma unroll 3
        for (int g2 = 0; g2 < NF; g2++) {
            float ar = __uint_as_float(atr[g2 * 56 + tid]);
            float ai = __uint_as_float(ati[g2 * 56 + tid]);
            s += ar * ar + ai * ai;
        }
        float w = (tid == 0 || tid == 32) ? 1.f : 2.f;
        sc[tid] = copysignf(1.f, tv) * rsqrtf(s) * w * (1.f / 64.f);
    }
    for (int i = tid; i < 6 * 56; i += 256) PT[66 * 56 + i] = 0u;
    __syncthreads();

    // ---- phase 5: apply  P[c][f] = sum_g V[c][g]*at[f][g]; store PT[2f][c] ----
    for (int t8 = warp; t8 < 18; t8 += 8) {
        int mt = t8 / 6, nt = t8 % 6;
        int m0 = mt * 16, n0 = nt * 8;
        float pR[4] = {0,0,0,0}, pI[4] = {0,0,0,0};
        #pragma unroll
        for (int kc = 0; kc < 5; kc++) {
            int kb = kc * 8;
            uint32_t vr0 = VT[(kb + tg)          * 56 + m0 + g];
            uint32_t vr1 = VT[(kb + tg)          * 56 + m0 + g + 8];
            uint32_t vr2 = VT[(kb + tg + 4)      * 56 + m0 + g];
            uint32_t vr3 = VT[(kb + tg + 4)      * 56 + m0 + g + 8];
            uint32_t vi0 = VT[(40 + kb + tg)     * 56 + m0 + g];
            uint32_t vi1 = VT[(40 + kb + tg)     * 56 + m0 + g + 8];
            uint32_t vi2 = VT[(40 + kb + tg + 4) * 56 + m0 + g];
            uint32_t vi3 = VT[(40 + kb + tg + 4) * 56 + m0 + g + 8];
            uint32_t bR0 = atr[(kb + tg)     * 56 + n0 + g];
            uint32_t bR1 = atr[(kb + tg + 4) * 56 + n0 + g];
            uint32_t bI0 = ati[(kb + tg)     * 56 + n0 + g];
            uint32_t bI1 = ati[(kb + tg + 4) * 56 + n0 + g];
            mma_tf32(pR, vr0, vr1, vr2, vr3, bR0, bR1);
            mma_tf32(pR, fneg(vi0), fneg(vi1), fneg(vi2), fneg(vi3), bI0, bI1);
            mma_tf32(pI, vr0, vr1, vr2, vr3, bI0, bI1);
            mma_tf32(pI, vi0, vi1, vi2, vi3, bR0, bR1);
        }
        int c0 = m0 + g, c1 = c0 + 8;
        int f0 = n0 + 2 * tg, f1 = f0 + 1;
        if (f0 < NF) {
            float s = sc[f0];
            PT[(2 * f0) * 56 + c0]     = f2tf(pR[0] * s);
            PT[(2 * f0 + 1) * 56 + c0] = f2tf(pI[0] * s);
            PT[(2 * f0) * 56 + c1]     = f2tf(pR[2] * s);
            PT[(2 * f0 + 1) * 56 + c1] = f2tf(pI[2] * s);
        }
        if (f1 < NF) {
            float s = sc[f1];
            PT[(2 * f1) * 56 + c0]     = f2tf(pR[1] * s);
            PT[(2 * f1 + 1) * 56 + c0] = f2tf(pI[1] * s);
            PT[(2 * f1) * 56 + c1]     = f2tf(pR[3] * s);
            PT[(2 * f1 + 1) * 56 + c1] = f2tf(pI[3] * s);
        }
    }
    __syncthreads();

    // ---- phase 6: irDFT  out[c][n] = sum_{2f} PT[2f][c] * Ds[n][2f] ----
    float* outBase = outp + ((size_t)b * C2 + head * CH) * HWIMG
                   + (size_t)(wy * 8) * IMW + wx * 8;
    for (int t8 = warp; t8 < 24; t8 += 8) {
        int mt = t8 / 8, nt = t8 % 8;
        int m0 = mt * 16, n0 = nt * 8;
        float acc[4] = {0.f, 0.f, 0.f, 0.f};
        #pragma unroll
        for (int kc = 0; kc < 9; kc++) {
            int kb = kc * 8;
            uint32_t a0 = PT[(kb + tg)     * 56 + m0 + g];
            uint32_t a1 = PT[(kb + tg)     * 56 + m0 + g + 8];
            uint32_t a2 = PT[(kb + tg + 4) * 56 + m0 + g];
            uint32_t a3 = PT[(kb + tg + 4) * 56 + m0 + g + 8];
            uint32_t b0 = Ds[(n0 + g) * 84 + kb + tg];
            uint32_t b1 = Ds[(n0 + g) * 84 + kb + tg + 4];
            mma_tf32(acc, a0, a1, a2, a3, b0, b1);
        }
        int c = m0 + g;
        *(float2*)&outBase[(size_t)c       * HWIMG + nt * IMW + 2 * tg] =
            make_float2(acc[0], acc[1]);
        *(float2*)&outBase[(size_t)(c + 8) * HWIMG + nt * IMW + 2 * tg] =
            make_float2(acc[2], acc[3]);
    }
}

// ---------------- launch ----------------
extern "C" void kernel_launch(void* const* d_in, const int* in_sizes, int n_in,
                              void* d_out, int out_size) {
    const float* x      = (const float*)d_in[0];
    const float* w_hid  = (const float*)d_in[1];
    const float* w_hdw  = (const float*)d_in[2];
    const float* w_proj = (const float*)d_in[3];
    const float* temp   = (const float*)d_in[4];
    const float* n1w    = (const float*)d_in[5];
    const float* n2w    = (const float*)d_in[6];
    const float* w_fin  = (const float*)d_in[7];
    const float* w_fdw  = (const float*)d_in[8];
    const float* w_fout = (const float*)d_in[9];
    float* out = (float*)d_out;

    float *h1, *h2, *att, *x1, *f1, *gg, *inv;
    cudaGetSymbolAddress((void**)&h1,  g_h1);
    cudaGetSymbolAddress((void**)&h2,  g_h2);
    cudaGetSymbolAddress((void**)&att, g_att);
    cudaGetSymbolAddress((void**)&x1,  g_x1);
    cudaGetSymbolAddress((void**)&f1,  g_f1);
    cudaGetSymbolAddress((void**)&gg,  g_g);
    cudaGetSymbolAddress((void**)&inv, g_inv);

    cudaFuncSetAttribute(attn_kernel, cudaFuncAttributeMaxDynamicSharedMemorySize,
                         ATTN_SMEM_FLOATS * 4);

    // 0) twiddle init
    dft_init_kernel<<<21, 256>>>();
    // 1) LN1 scale
    ln_scale_kernel<<<dim3(256, BDIM), 256>>>(x, inv);
    // 2) to_hidden 1x1 (96 -> 576), LN fused
    gemm_tf32_kernel<false><<<dim3(512, 5, BDIM), 256>>>(w_hid, x, nullptr, n1w, inv, h1, C6, CDIM);
    // 3) dwconv 3x3 (tiled, float4)
    dwconv_kernel<<<dim3(32, C6, BDIM), 256>>>(h1, w_hdw, h2, C6);
    // 4) windowed FFT attention (full-MMA)
    attn_kernel<<<dim3(1024, HEADS, BDIM), 256, ATTN_SMEM_FLOATS * 4>>>(h2, temp, att);
    // 5) project_out 1x1 (192 -> 96) + residual x
    gemm_tf32_kernel<true><<<dim3(512, 1, BDIM), 256>>>(w_proj, att, x, nullptr, nullptr, x1, CDIM, C2);
    // 6) LN2 scale
    ln_scale_kernel<<<dim3(256, BDIM), 256>>>(x1, inv);
    // 7) ffn in 1x1 (96 -> 510), LN fused
    gemm_tf32_kernel<false><<<dim3(512, 4, BDIM), 256>>>(w_fin, x1, nullptr, n2w, inv, f1, CHID2, CDIM);
    // 8) fused dwconv + gelu gate
    dwgate_kernel<<<dim3(32, CHID, BDIM), 256>>>(f1, w_fdw, gg);
    // 9) ffn out 1x1 (255 -> 96) + residual x1 -> d_out
    gemm_tf32_kernel<true><<<dim3(512, 1, BDIM), 256>>>(w_fout, gg, x1, nullptr, nullptr, out, CDIM, CHID);
}

// round 10
// speedup vs baseline: 1.5017x; 1.0945x over previous
#include <cuda_runtime.h>
#include <math.h>
#include <stdint.h>

// ---------------- problem constants ----------------
#define IMW   256
#define HWIMG 65536          // 256*256
#define BDIM  2
#define CDIM  96
#define C6    576            // 6*DIM
#define C2    192            // 2*DIM
#define CHID  255            // hidden_features
#define CHID2 510            // 2*hidden
#define HEADS 4
#define CH    48             // channels per head
#define NF    33             // rfft bins of 64

// ---------------- scratch ----------------
__device__ float g_h1 [(size_t)BDIM * C6    * HWIMG];
__device__ float g_h2 [(size_t)BDIM * C6    * HWIMG];
__device__ float g_att[(size_t)BDIM * C2    * HWIMG];
__device__ float g_x1 [(size_t)BDIM * CDIM  * HWIMG];
__device__ float g_f1 [(size_t)BDIM * CHID2 * HWIMG];
__device__ float g_g  [(size_t)BDIM * CHID  * HWIMG];
__device__ float g_inv[(size_t)BDIM * HWIMG];
__device__ uint32_t g_dft[64 * 84];   // Ds[n][2f]=cos, [2f+1]=-sin, cols>=66 zero

__device__ __forceinline__ uint32_t f2tf(float f) {
    uint32_t u;
    asm("cvt.rna.tf32.f32 %0, %1;" : "=r"(u) : "f"(f));
    return u;
}
__device__ __forceinline__ uint32_t fneg(uint32_t u) { return u ^ 0x80000000u; }

__device__ __forceinline__ void mma_tf32(float* d, uint32_t a0, uint32_t a1,
                                         uint32_t a2, uint32_t a3,
                                         uint32_t b0, uint32_t b1) {
    asm volatile(
        "mma.sync.aligned.m16n8k8.row.col.f32.tf32.tf32.f32 "
        "{%0,%1,%2,%3}, {%4,%5,%6,%7}, {%8,%9}, {%0,%1,%2,%3};\n"
        : "+f"(d[0]), "+f"(d[1]), "+f"(d[2]), "+f"(d[3])
        : "r"(a0), "r"(a1), "r"(a2), "r"(a3), "r"(b0), "r"(b1));
}

__device__ __forceinline__ void cp_async16(uint32_t smem_addr, const void* gptr) {
    asm volatile("cp.async.cg.shared.global [%0], [%1], 16;\n"
                 :: "r"(smem_addr), "l"(gptr));
}

// ---------------- twiddle init ----------------
__global__ void dft_init_kernel() {
    int i = blockIdx.x * 256 + threadIdx.x;
    if (i >= 64 * 84) return;
    int n = i / 84, col = i % 84, f = col >> 1;
    float v = 0.f;
    if (col < 66) {
        float ang = 6.2831853071795864f * (float)((f * n) & 63) / 64.f;
        v = (col & 1) ? -sinf(ang) : cosf(ang);
    }
    g_dft[i] = f2tf(v);
}

// ---------------- LN scale only ----------------
__global__ void ln_scale_kernel(const float* __restrict__ x, float* __restrict__ inv) {
    int pix = blockIdx.x * 256 + threadIdx.x;
    int b   = blockIdx.y;
    const float* xb = x + (size_t)b * CDIM * HWIMG + pix;
    float s = 0.f, s2 = 0.f;
    #pragma unroll 8
    for (int c = 0; c < CDIM; c++) {
        float v = xb[(size_t)c * HWIMG];
        s += v; s2 += v * v;
    }
    float mean = s * (1.0f / CDIM);
    float var  = s2 * (1.0f / CDIM) - mean * mean;
    inv[(size_t)b * HWIMG + pix] = rsqrtf(var + 1e-5f);
}

// ---------------- tf32 conv1x1 GEMM: cp.async double-buffered ----------------
#define GBM 128
#define GBN 128
#define GBK 32
#define GPAD 8
#define GP   (GBM + GPAD)    // 136 (same for N)
#define AS(st,k,m) Asb[((st) * GBK + (k)) * GP + (m)]
#define BS(st,k,n) Bsb[((st) * GBK + (k)) * GP + (n)]
#define GEMM_SMEM_BYTES (2 * GBK * GP * 2 * 4)   // 69632

template<bool RESID>
__global__ void __launch_bounds__(256) gemm_tf32_kernel(
        const float* __restrict__ A, const float* __restrict__ X,
        const float* __restrict__ R, const float* __restrict__ nw,
        const float* __restrict__ cs, float* __restrict__ Y, int M, int K) {
    extern __shared__ uint32_t gsm[];
    uint32_t* Asb = gsm;
    uint32_t* Bsb = gsm + 2 * GBK * GP;

    int tid  = threadIdx.x;
    int warp = tid >> 5, lane = tid & 31;
    int g    = lane >> 2, tg = lane & 3;
    int wm   = (warp & 1) * 64;
    int wn   = (warp >> 1) * 32;

    int bn = blockIdx.x * GBN;
    int bm = blockIdx.y * GBM;
    int b  = blockIdx.z;
    const float* Xb = X + (size_t)b * K * HWIMG + bn;

    float acc[4][4][4];
    #pragma unroll
    for (int mt = 0; mt < 4; mt++)
        #pragma unroll
        for (int nt = 0; nt < 4; nt++)
            #pragma unroll
            for (int i = 0; i < 4; i++) acc[mt][nt][i] = 0.f;

    int xk = tid >> 3;
    int xc = (tid & 7) * 4;
    int nIter = (K + GBK - 1) / GBK;

    auto loadTiles = [&](int it, int st) {
        int k0 = it * GBK;
        // A tile: LDG + rna-round + nw fold (tiny)
        #pragma unroll
        for (int i = 0; i < 16; i++) {
            int lin = tid + i * 256;
            int m = lin & 127, k = lin >> 7;
            int gm = bm + m, gk = k0 + k;
            float v = (gm < M && gk < K) ? A[(size_t)gm * K + gk] : 0.f;
            if (nw && gk < K) v *= nw[gk];
            AS(st, k, m) = f2tf(v);
        }
        // B tile: raw fp32 via cp.async (tf32 mma truncates mantissa in HW)
        int gk = k0 + xk;
        if (gk < K) {
            const float* p = Xb + (size_t)gk * HWIMG + xc;
            uint32_t sa = (uint32_t)__cvta_generic_to_shared(&BS(st, xk, xc));
            #pragma unroll
            for (int j = 0; j < 4; j++)
                cp_async16(sa + j * 128, p + j * 32);
        } else {
            uint4 z = make_uint4(0u, 0u, 0u, 0u);
            #pragma unroll
            for (int j = 0; j < 4; j++)
                *(uint4*)&BS(st, xk, xc + j * 32) = z;
        }
    };

    loadTiles(0, 0);
    asm volatile("cp.async.commit_group;\n" ::: "memory");

    for (int it = 0; it < nIter; it++) {
        int st = it & 1;
        if (it + 1 < nIter) {
            loadTiles(it + 1, st ^ 1);
            asm volatile("cp.async.commit_group;\n" ::: "memory");
            asm volatile("cp.async.wait_group 1;\n" ::: "memory");
        } else {
            asm volatile("cp.async.wait_group 0;\n" ::: "memory");
        }
        __syncthreads();

        #pragma unroll
        for (int ks = 0; ks < 4; ks++) {
            int kb = ks * 8;
            uint32_t af[4][4], bf[4][2];
            #pragma unroll
            for (int mt = 0; mt < 4; mt++) {
                int m0 = wm + mt * 16;
                af[mt][0] = AS(st, kb + tg,     m0 + g);
                af[mt][1] = AS(st, kb + tg,     m0 + g + 8);
                af[mt][2] = AS(st, kb + tg + 4, m0 + g);
                af[mt][3] = AS(st, kb + tg + 4, m0 + g + 8);
            }
            #pragma unroll
            for (int nt = 0; nt < 4; nt++) {
                int n0 = wn + nt * 8;
                bf[nt][0] = BS(st, kb + tg,     n0 + g);
                bf[nt][1] = BS(st, kb + tg + 4, n0 + g);
            }
            #pragma unroll
            for (int mt = 0; mt < 4; mt++)
                #pragma unroll
                for (int nt = 0; nt < 4; nt++)
                    mma_tf32(acc[mt][nt], af[mt][0], af[mt][1], af[mt][2], af[mt][3],
                             bf[nt][0], bf[nt][1]);
        }
        __syncthreads();
    }

    #pragma unroll
    for (int nt = 0; nt < 4; nt++) {
        int n = bn + wn + nt * 8 + 2 * tg;
        float2 sc = make_float2(1.f, 1.f);
        if (cs) sc = *(const float2*)(cs + (size_t)b * HWIMG + n);
        #pragma unroll
        for (int mt = 0; mt < 4; mt++) {
            int m0 = bm + wm + mt * 16 + g;
            int m1 = m0 + 8;
            if (m0 < M) {
                size_t off = ((size_t)b * M + m0) * HWIMG + n;
                float2 o = make_float2(acc[mt][nt][0] * sc.x, acc[mt][nt][1] * sc.y);
                if (RESID) {
                    float2 r = *(const float2*)(R + off);
                    o.x += r.x; o.y += r.y;
                }
                *(float2*)(Y + off) = o;
            }
            if (m1 < M) {
                size_t off = ((size_t)b * M + m1) * HWIMG + n;
                float2 o = make_float2(acc[mt][nt][2] * sc.x, acc[mt][nt][3] * sc.y);
                if (RESID) {
                    float2 r = *(const float2*)(R + off);
                    o.x += r.x; o.y += r.y;
                }
                *(float2*)(Y + off) = o;
            }
        }
    }
}

// ---------------- tiled depthwise 3x3 (float4 loads, pitch 76) ----------------
#define DWP 76

__device__ __forceinline__ void dw_load_tile4(const float* __restrict__ ip,
                                              float* __restrict__ tile,
                                              int y0, int x0, int tid) {
    for (int i = tid; i < 34 * 18; i += 256) {
        int r = i / 18, k = i - r * 18;
        int gy = y0 - 1 + r;
        int gx = x0 - 4 + k * 4;
        float4 v = make_float4(0.f, 0.f, 0.f, 0.f);
        if (gy >= 0 && gy < 256 && gx >= 0 && gx < 256)
            v = *(const float4*)(ip + gy * IMW + gx);
        *(float4*)&tile[r * DWP + k * 4] = v;
    }
}

__device__ __forceinline__ void dw_compute8(const float* __restrict__ tile,
                                            const float* __restrict__ wr,
                                            int row, int col0, float* o) {
    float r0[10], r1[10], r2[10];
    const float* t0 = tile + row * DWP + col0 + 3;
    #pragma unroll
    for (int j = 0; j < 10; j++) {
        r0[j] = t0[j];
        r1[j] = t0[DWP + j];
        r2[j] = t0[2 * DWP + j];
    }
    #pragma unroll
    for (int j = 0; j < 8; j++) {
        o[j] = r0[j] * wr[0] + r0[j+1] * wr[1] + r0[j+2] * wr[2]
             + r1[j] * wr[3] + r1[j+1] * wr[4] + r1[j+2] * wr[5]
             + r2[j] * wr[6] + r2[j+1] * wr[7] + r2[j+2] * wr[8];
    }
}

__global__ void __launch_bounds__(256) dwconv_kernel(
        const float* __restrict__ in, const float* __restrict__ w,
        float* __restrict__ out, int C) {
    __shared__ float tile[34 * DWP];
    int tid = threadIdx.x;
    int t   = blockIdx.x;
    int c   = blockIdx.y, b = blockIdx.z;
    int y0  = (t >> 2) * 32, x0 = (t & 3) * 64;

    const float* ip = in + ((size_t)b * C + c) * HWIMG;
    dw_load_tile4(ip, tile, y0, x0, tid);
    float wr[9];
    #pragma unroll
    for (int j = 0; j < 9; j++) wr[j] = w[c * 9 + j];
    __syncthreads();

    int row = tid >> 3, col0 = (tid & 7) * 8;
    float o[8];
    dw_compute8(tile, wr, row, col0, o);
    float* op = out + ((size_t)b * C + c) * HWIMG + (y0 + row) * IMW + x0 + col0;
    *(float4*)op       = make_float4(o[0], o[1], o[2], o[3]);
    *(float4*)(op + 4) = make_float4(o[4], o[5], o[6], o[7]);
}

__global__ void __launch_bounds__(256) dwgate_kernel(
        const float* __restrict__ in, const float* __restrict__ w,
        float* __restrict__ gout) {
    __shared__ float tile1[34 * DWP];
    __shared__ float tile2[34 * DWP];
    int tid = threadIdx.x;
    int t   = blockIdx.x;
    int c   = blockIdx.y, b = blockIdx.z;
    int y0  = (t >> 2) * 32, x0 = (t & 3) * 64;

    const float* ip1 = in + ((size_t)b * CHID2 + c) * HWIMG;
    const float* ip2 = in + ((size_t)b * CHID2 + CHID + c) * HWIMG;
    dw_load_tile4(ip1, tile1, y0, x0, tid);
    dw_load_tile4(ip2, tile2, y0, x0, tid);
    float wr1[9], wr2[9];
    #pragma unroll
    for (int j = 0; j < 9; j++) {
        wr1[j] = w[c * 9 + j];
        wr2[j] = w[(CHID + c) * 9 + j];
    }
    __syncthreads();

    int row = tid >> 3, col0 = (tid & 7) * 8;
    float v1[8], v2[8];
    dw_compute8(tile1, wr1, row, col0, v1);
    dw_compute8(tile2, wr2, row, col0, v2);
    float o[8];
    #pragma unroll
    for (int j = 0; j < 8; j++) {
        float ge = 0.5f * v1[j] * (1.f + erff(v1[j] * 0.70710678118654752f));
        o[j] = ge * v2[j];
    }
    float* op = gout + ((size_t)b * CHID + c) * HWIMG + (y0 + row) * IMW + x0 + col0;
    *(float4*)op       = make_float4(o[0], o[1], o[2], o[3]);
    *(float4*)(op + 4) = make_float4(o[4], o[5], o[6], o[7]);
}

// ---------------- windowed FFT attention: ALL contractions on tensor pipe ----------------
#define SM_DS  0
#define SM_SX  5376
#define SM_ATR 5376
#define SM_ATI 7616
#define SM_PT  9856
#define SM_QKT 15104
#define SM_VT  23168
#define SM_SC  27648
#define ATTN_SMEM_FLOATS 27688

__global__ void __launch_bounds__(256) attn_kernel(
        const float* __restrict__ qkv, const float* __restrict__ temp,
        float* __restrict__ outp) {
    extern __shared__ float sm[];
    uint32_t* Ds  = (uint32_t*)(sm + SM_DS);
    uint32_t* sx  = (uint32_t*)(sm + SM_SX);
    uint32_t* atr = (uint32_t*)(sm + SM_ATR);
    uint32_t* ati = (uint32_t*)(sm + SM_ATI);
    uint32_t* PT  = (uint32_t*)(sm + SM_PT);
    uint32_t* QKT = (uint32_t*)(sm + SM_QKT);
    uint32_t* VT  = (uint32_t*)(sm + SM_VT);
    float*    sc  = sm + SM_SC;

    int tid  = threadIdx.x;
    int warp = tid >> 5, lane = tid & 31;
    int g    = lane >> 2, tg = lane & 3;
    int wy   = blockIdx.x >> 5, wx = blockIdx.x & 31;
    int head = blockIdx.y, b = blockIdx.z;
    float tv = temp[head];

    size_t base = ((size_t)b * C6 + head * CH) * HWIMG + (size_t)(wy * 8) * IMW + wx * 8;

    for (int i = tid; i < 64 * 84; i += 256) Ds[i] = g_dft[i];
    for (int i = tid; i < 3 * CH * 64; i += 256) {
        int t = i / 3072, rem = i - t * 3072;
        int c = rem >> 6, n = rem & 63;
        float v = qkv[base + (size_t)(t * C2 + c) * HWIMG + (n >> 3) * IMW + (n & 7)];
        sx[n * 152 + t * CH + c] = f2tf(v);
    }
    __syncthreads();

    // DFT  QFT[fcomp][c] = sum_t E[fcomp][t] * X[c][t]
    for (int t8 = warp; t8 < 90; t8 += 8) {
        int mt = t8 / 18, nt = t8 % 18;
        int m0 = mt * 16, n0 = nt * 8;
        int mA = m0 + g, mB = mA + 8;
        int colA = (mA < 40) ? 2 * mA : 2 * (mA - 40) + 1;
        int colB = (mB < 40) ? 2 * mB : 2 * (mB - 40) + 1;
        float acc[4] = {0.f, 0.f, 0.f, 0.f};
        #pragma unroll
        for (int kc = 0; kc < 8; kc++) {
            int kb = kc * 8;
            uint32_t a0 = Ds[(kb + tg)     * 84 + colA];
            uint32_t a1 = Ds[(kb + tg)     * 84 + colB];
            uint32_t a2 = Ds[(kb + tg + 4) * 84 + colA];
            uint32_t a3 = Ds[(kb + tg + 4) * 84 + colB];
            uint32_t b0 = sx[(kb + tg)     * 152 + n0 + g];
            uint32_t b1 = sx[(kb + tg + 4) * 152 + n0 + g];
            mma_tf32(acc, a0, a1, a2, a3, b0, b1);
        }
        int c0 = n0 + 2 * tg;
        if (n0 < 96) {
            QKT[c0 * 84 + mA]       = f2tf(acc[0]);
            QKT[(c0 + 1) * 84 + mA] = f2tf(acc[1]);
            QKT[c0 * 84 + mB]       = f2tf(acc[2]);
            QKT[(c0 + 1) * 84 + mB] = f2tf(acc[3]);
        } else {
            int cv = c0 - 96;
            VT[mA * 56 + cv]     = f2tf(acc[0]);
            VT[mA * 56 + cv + 1] = f2tf(acc[1]);
            VT[mB * 56 + cv]     = f2tf(acc[2]);
            VT[mB * 56 + cv + 1] = f2tf(acc[3]);
        }
    }
    __syncthreads();

    // gram -> atT[g][f]
    for (int t8 = warp; t8 < 15; t8 += 8) {
        int mt = t8 / 5, nt = t8 % 5;
        int m0 = mt * 16, n0 = nt * 8;
        int fA = m0 + g, fB = fA + 8;
        int ciA = 40 + ((fA < 40) ? fA : 0);
        int ciB = 40 + ((fB < 40) ? fB : 0);
        float aR[4] = {0,0,0,0}, aI[4] = {0,0,0,0};
        #pragma unroll
        for (int kc = 0; kc < 6; kc++) {
            int kb = kc * 8;
            uint32_t qr0 = QKT[(kb + tg)     * 84 + fA];
            uint32_t qr1 = QKT[(kb + tg)     * 84 + fB];
            uint32_t qr2 = QKT[(kb + tg + 4) * 84 + fA];
            uint32_t qr3 = QKT[(kb + tg + 4) * 84 + fB];
            uint32_t qi0 = QKT[(kb + tg)     * 84 + ciA];
            uint32_t qi1 = QKT[(kb + tg)     * 84 + ciB];
            uint32_t qi2 = QKT[(kb + tg + 4) * 84 + ciA];
            uint32_t qi3 = QKT[(kb + tg + 4) * 84 + ciB];
            uint32_t kr0 = QKT[(48 + kb + tg)     * 84 + n0 + g];
            uint32_t kr1 = QKT[(48 + kb + tg + 4) * 84 + n0 + g];
            uint32_t ki0 = QKT[(48 + kb + tg)     * 84 + 40 + n0 + g];
            uint32_t ki1 = QKT[(48 + kb + tg + 4) * 84 + 40 + n0 + g];
            mma_tf32(aR, qr0, qr1, qr2, qr3, kr0, kr1);
            mma_tf32(aR, qi0, qi1, qi2, qi3, fneg(ki0), fneg(ki1));
            mma_tf32(aI, qr0, qr1, qr2, qr3, ki0, ki1);
            mma_tf32(aI, qi0, qi1, qi2, qi3, kr0, kr1);
        }
        int gc0 = n0 + 2 * tg, gc1 = gc0 + 1;
        atr[gc0 * 56 + fA] = f2tf(aR[0]);  ati[gc0 * 56 + fA] = f2tf(aI[0]);
        atr[gc1 * 56 + fA] = f2tf(aR[1]);  ati[gc1 * 56 + fA] = f2tf(aI[1]);
        atr[gc0 * 56 + fB] = f2tf(aR[2]);  ati[gc0 * 56 + fB] = f2tf(aI[2]);
        atr[gc1 * 56 + fB] = f2tf(aR[3]);  ati[gc1 * 56 + fB] = f2tf(aI[3]);
    }
    __syncthreads();

    // row norms -> scale[f]; zero PT pad rows
    if (tid < NF) {
        float s = 0.f;
        #pragma unroll 3
        for (int g2 = 0; g2 < NF; g2++) {
            float ar = __uint_as_float(atr[g2 * 56 + tid]);
            float ai = __uint_as_float(ati[g2 * 56 + tid]);
            s += ar * ar + ai * ai;
        }
        float w = (tid == 0 || tid == 32) ? 1.f : 2.f;
        sc[tid] = copysignf(1.f, tv) * rsqrtf(s) * w * (1.f / 64.f);
    }
    for (int i = tid; i < 6 * 56; i += 256) PT[66 * 56 + i] = 0u;
    __syncthreads();

    // apply -> PT[2f][c]
    for (int t8 = warp; t8 < 18; t8 += 8) {
        int mt = t8 / 6, nt = t8 % 6;
        int m0 = mt * 16, n0 = nt * 8;
        float pR[4] = {0,0,0,0}, pI[4] = {0,0,0,0};
        #pragma unroll
        for (int kc = 0; kc < 5; kc++) {
            int kb = kc * 8;
            uint32_t vr0 = VT[(kb + tg)          * 56 + m0 + g];
            uint32_t vr1 = VT[(kb + tg)          * 56 + m0 + g + 8];
            uint32_t vr2 = VT[(kb + tg + 4)      * 56 + m0 + g];
            uint32_t vr3 = VT[(kb + tg + 4)      * 56 + m0 + g + 8];
            uint32_t vi0 = VT[(40 + kb + tg)     * 56 + m0 + g];
            uint32_t vi1 = VT[(40 + kb + tg)     * 56 + m0 + g + 8];
            uint32_t vi2 = VT[(40 + kb + tg + 4) * 56 + m0 + g];
            uint32_t vi3 = VT[(40 + kb + tg + 4) * 56 + m0 + g + 8];
            uint32_t bR0 = atr[(kb + tg)     * 56 + n0 + g];
            uint32_t bR1 = atr[(kb + tg + 4) * 56 + n0 + g];
            uint32_t bI0 = ati[(kb + tg)     * 56 + n0 + g];
            uint32_t bI1 = ati[(kb + tg + 4) * 56 + n0 + g];
            mma_tf32(pR, vr0, vr1, vr2, vr3, bR0, bR1);
            mma_tf32(pR, fneg(vi0), fneg(vi1), fneg(vi2), fneg(vi3), bI0, bI1);
            mma_tf32(pI, vr0, vr1, vr2, vr3, bI0, bI1);
            mma_tf32(pI, vi0, vi1, vi2, vi3, bR0, bR1);
        }
        int c0 = m0 + g, c1 = c0 + 8;
        int f0 = n0 + 2 * tg, f1 = f0 + 1;
        if (f0 < NF) {
            float s = sc[f0];
            PT[(2 * f0) * 56 + c0]     = f2tf(pR[0] * s);
            PT[(2 * f0 + 1) * 56 + c0] = f2tf(pI[0] * s);
            PT[(2 * f0) * 56 + c1]     = f2tf(pR[2] * s);
            PT[(2 * f0 + 1) * 56 + c1] = f2tf(pI[2] * s);
        }
        if (f1 < NF) {
            float s = sc[f1];
            PT[(2 * f1) * 56 + c0]     = f2tf(pR[1] * s);
            PT[(2 * f1 + 1) * 56 + c0] = f2tf(pI[1] * s);
            PT[(2 * f1) * 56 + c1]     = f2tf(pR[3] * s);
            PT[(2 * f1 + 1) * 56 + c1] = f2tf(pI[3] * s);
        }
    }
    __syncthreads();

    // irDFT
    float* outBase = outp + ((size_t)b * C2 + head * CH) * HWIMG
                   + (size_t)(wy * 8) * IMW + wx * 8;
    for (int t8 = warp; t8 < 24; t8 += 8) {
        int mt = t8 / 8, nt = t8 % 8;
        int m0 = mt * 16, n0 = nt * 8;
        float acc[4] = {0.f, 0.f, 0.f, 0.f};
        #pragma unroll
        for (int kc = 0; kc < 9; kc++) {
            int kb = kc * 8;
            uint32_t a0 = PT[(kb + tg)     * 56 + m0 + g];
            uint32_t a1 = PT[(kb + tg)     * 56 + m0 + g + 8];
            uint32_t a2 = PT[(kb + tg + 4) * 56 + m0 + g];
            uint32_t a3 = PT[(kb + tg + 4) * 56 + m0 + g + 8];
            uint32_t b0 = Ds[(n0 + g) * 84 + kb + tg];
            uint32_t b1 = Ds[(n0 + g) * 84 + kb + tg + 4];
            mma_tf32(acc, a0, a1, a2, a3, b0, b1);
        }
        int c = m0 + g;
        *(float2*)&outBase[(size_t)c       * HWIMG + nt * IMW + 2 * tg] =
            make_float2(acc[0], acc[1]);
        *(float2*)&outBase[(size_t)(c + 8) * HWIMG + nt * IMW + 2 * tg] =
            make_float2(acc[2], acc[3]);
    }
}

// ---------------- launch ----------------
extern "C" void kernel_launch(void* const* d_in, const int* in_sizes, int n_in,
                              void* d_out, int out_size) {
    const float* x      = (const float*)d_in[0];
    const float* w_hid  = (const float*)d_in[1];
    const float* w_hdw  = (const float*)d_in[2];
    const float* w_proj = (const float*)d_in[3];
    const float* temp   = (const float*)d_in[4];
    const float* n1w    = (const float*)d_in[5];
    const float* n2w    = (const float*)d_in[6];
    const float* w_fin  = (const float*)d_in[7];
    const float* w_fdw  = (const float*)d_in[8];
    const float* w_fout = (const float*)d_in[9];
    float* out = (float*)d_out;

    float *h1, *h2, *att, *x1, *f1, *gg, *inv;
    cudaGetSymbolAddress((void**)&h1,  g_h1);
    cudaGetSymbolAddress((void**)&h2,  g_h2);
    cudaGetSymbolAddress((void**)&att, g_att);
    cudaGetSymbolAddress((void**)&x1,  g_x1);
    cudaGetSymbolAddress((void**)&f1,  g_f1);
    cudaGetSymbolAddress((void**)&gg,  g_g);
    cudaGetSymbolAddress((void**)&inv, g_inv);

    cudaFuncSetAttribute(attn_kernel, cudaFuncAttributeMaxDynamicSharedMemorySize,
                         ATTN_SMEM_FLOATS * 4);
    cudaFuncSetAttribute(gemm_tf32_kernel<false>,
                         cudaFuncAttributeMaxDynamicSharedMemorySize, GEMM_SMEM_BYTES);
    cudaFuncSetAttribute(gemm_tf32_kernel<true>,
                         cudaFuncAttributeMaxDynamicSharedMemorySize, GEMM_SMEM_BYTES);

    // 0) twiddle init
    dft_init_kernel<<<21, 256>>>();
    // 1) LN1 scale
    ln_scale_kernel<<<dim3(256, BDIM), 256>>>(x, inv);
    // 2) to_hidden 1x1 (96 -> 576), LN fused
    gemm_tf32_kernel<false><<<dim3(512, 5, BDIM), 256, GEMM_SMEM_BYTES>>>(
        w_hid, x, nullptr, n1w, inv, h1, C6, CDIM);
    // 3) dwconv 3x3 (tiled, float4)
    dwconv_kernel<<<dim3(32, C6, BDIM), 256>>>(h1, w_hdw, h2, C6);
    // 4) windowed FFT attention (full-MMA)
    attn_kernel<<<dim3(1024, HEADS, BDIM), 256, ATTN_SMEM_FLOATS * 4>>>(h2, temp, att);
    // 5) project_out 1x1 (192 -> 96) + residual x
    gemm_tf32_kernel<true><<<dim3(512, 1, BDIM), 256, GEMM_SMEM_BYTES>>>(
        w_proj, att, x, nullptr, nullptr, x1, CDIM, C2);
    // 6) LN2 scale
    ln_scale_kernel<<<dim3(256, BDIM), 256>>>(x1, inv);
    // 7) ffn in 1x1 (96 -> 510), LN fused
    gemm_tf32_kernel<false><<<dim3(512, 4, BDIM), 256, GEMM_SMEM_BYTES>>>(
        w_fin, x1, nullptr, n2w, inv, f1, CHID2, CDIM);
    // 8) fused dwconv + gelu gate
    dwgate_kernel<<<dim3(32, CHID, BDIM), 256>>>(f1, w_fdw, gg);
    // 9) ffn out 1x1 (255 -> 96) + residual x1 -> d_out
    gemm_tf32_kernel<true><<<dim3(512, 1, BDIM), 256, GEMM_SMEM_BYTES>>>(
        w_fout, gg, x1, nullptr, nullptr, out, CDIM, CHID);
}

// round 11
// speedup vs baseline: 1.5029x; 1.0008x over previous
#include <cuda_runtime.h>
#include <math.h>
#include <stdint.h>

// ---------------- problem constants ----------------
#define IMW   256
#define HWIMG 65536          // 256*256
#define BDIM  2
#define CDIM  96
#define C6    576            // 6*DIM
#define C2    192            // 2*DIM
#define CHID  255            // hidden_features
#define CHID2 510            // 2*hidden
#define HEADS 4
#define CH    48             // channels per head
#define NF    33             // rfft bins of 64

// ---------------- scratch ----------------
__device__ float g_h1 [(size_t)BDIM * C6    * HWIMG];
__device__ float g_h2 [(size_t)BDIM * C6    * HWIMG];
__device__ float g_att[(size_t)BDIM * C2    * HWIMG];
__device__ float g_x1 [(size_t)BDIM * CDIM  * HWIMG];
__device__ float g_f1 [(size_t)BDIM * CHID2 * HWIMG];
__device__ float g_g  [(size_t)BDIM * CHID  * HWIMG];
__device__ float g_inv[(size_t)BDIM * HWIMG];
__device__ uint32_t g_dft[64 * 84];   // Ds[n][2f]=cos, [2f+1]=-sin, cols>=66 zero

__device__ __forceinline__ uint32_t f2tf(float f) {
    uint32_t u;
    asm("cvt.rna.tf32.f32 %0, %1;" : "=r"(u) : "f"(f));
    return u;
}
__device__ __forceinline__ uint32_t fneg(uint32_t u) { return u ^ 0x80000000u; }

__device__ __forceinline__ void mma_tf32(float* d, uint32_t a0, uint32_t a1,
                                         uint32_t a2, uint32_t a3,
                                         uint32_t b0, uint32_t b1) {
    asm volatile(
        "mma.sync.aligned.m16n8k8.row.col.f32.tf32.tf32.f32 "
        "{%0,%1,%2,%3}, {%4,%5,%6,%7}, {%8,%9}, {%0,%1,%2,%3};\n"
        : "+f"(d[0]), "+f"(d[1]), "+f"(d[2]), "+f"(d[3])
        : "r"(a0), "r"(a1), "r"(a2), "r"(a3), "r"(b0), "r"(b1));
}

__device__ __forceinline__ void cp_async16(uint32_t smem_addr, const void* gptr) {
    asm volatile("cp.async.cg.shared.global [%0], [%1], 16;\n"
                 :: "r"(smem_addr), "l"(gptr));
}

// ---------------- twiddle init ----------------
__global__ void dft_init_kernel() {
    int i = blockIdx.x * 256 + threadIdx.x;
    if (i >= 64 * 84) return;
    int n = i / 84, col = i % 84, f = col >> 1;
    float v = 0.f;
    if (col < 66) {
        float ang = 6.2831853071795864f * (float)((f * n) & 63) / 64.f;
        v = (col & 1) ? -sinf(ang) : cosf(ang);
    }
    g_dft[i] = f2tf(v);
}

// ---------------- LN scale only ----------------
__global__ void ln_scale_kernel(const float* __restrict__ x, float* __restrict__ inv) {
    int pix = blockIdx.x * 256 + threadIdx.x;
    int b   = blockIdx.y;
    const float* xb = x + (size_t)b * CDIM * HWIMG + pix;
    float s = 0.f, s2 = 0.f;
    #pragma unroll 8
    for (int c = 0; c < CDIM; c++) {
        float v = xb[(size_t)c * HWIMG];
        s += v; s2 += v * v;
    }
    float mean = s * (1.0f / CDIM);
    float var  = s2 * (1.0f / CDIM) - mean * mean;
    inv[(size_t)b * HWIMG + pix] = rsqrtf(var + 1e-5f);
}

// ---------------- tf32 conv1x1 GEMM: cp.async double-buffered ----------------
#define GBM 128
#define GBN 128
#define GBK 32
#define GPAD 8
#define GP   (GBM + GPAD)    // 136 (same for N)
#define AS(st,k,m) Asb[((st) * GBK + (k)) * GP + (m)]
#define BS(st,k,n) Bsb[((st) * GBK + (k)) * GP + (n)]
#define GEMM_SMEM_BYTES (2 * GBK * GP * 2 * 4)   // 69632

template<bool RESID>
__global__ void __launch_bounds__(256) gemm_tf32_kernel(
        const float* __restrict__ A, const float* __restrict__ X,
        const float* __restrict__ R, const float* __restrict__ nw,
        const float* __restrict__ cs, float* __restrict__ Y, int M, int K) {
    extern __shared__ uint32_t gsm[];
    uint32_t* Asb = gsm;
    uint32_t* Bsb = gsm + 2 * GBK * GP;

    int tid  = threadIdx.x;
    int warp = tid >> 5, lane = tid & 31;
    int g    = lane >> 2, tg = lane & 3;
    int wm   = (warp & 1) * 64;
    int wn   = (warp >> 1) * 32;

    int bn = blockIdx.x * GBN;
    int bm = blockIdx.y * GBM;
    int b  = blockIdx.z;
    const float* Xb = X + (size_t)b * K * HWIMG + bn;

    float acc[4][4][4];
    #pragma unroll
    for (int mt = 0; mt < 4; mt++)
        #pragma unroll
        for (int nt = 0; nt < 4; nt++)
            #pragma unroll
            for (int i = 0; i < 4; i++) acc[mt][nt][i] = 0.f;

    int xk = tid >> 3;
    int xc = (tid & 7) * 4;
    int nIter = (K + GBK - 1) / GBK;

    auto loadTiles = [&](int it, int st) {
        int k0 = it * GBK;
        // A tile: LDG + rna-round + nw fold (tiny)
        #pragma unroll
        for (int i = 0; i < 16; i++) {
            int lin = tid + i * 256;
            int m = lin & 127, k = lin >> 7;
            int gm = bm + m, gk = k0 + k;
            float v = (gm < M && gk < K) ? A[(size_t)gm * K + gk] : 0.f;
            if (nw && gk < K) v *= nw[gk];
            AS(st, k, m) = f2tf(v);
        }
        // B tile: raw fp32 via cp.async (tf32 mma truncates mantissa in HW)
        int gk = k0 + xk;
        if (gk < K) {
            const float* p = Xb + (size_t)gk * HWIMG + xc;
            uint32_t sa = (uint32_t)__cvta_generic_to_shared(&BS(st, xk, xc));
            #pragma unroll
            for (int j = 0; j < 4; j++)
                cp_async16(sa + j * 128, p + j * 32);
        } else {
            uint4 z = make_uint4(0u, 0u, 0u, 0u);
            #pragma unroll
            for (int j = 0; j < 4; j++)
                *(uint4*)&BS(st, xk, xc + j * 32) = z;
        }
    };

    loadTiles(0, 0);
    asm volatile("cp.async.commit_group;\n" ::: "memory");

    for (int it = 0; it < nIter; it++) {
        int st = it & 1;
        if (it + 1 < nIter) {
            loadTiles(it + 1, st ^ 1);
            asm volatile("cp.async.commit_group;\n" ::: "memory");
            asm volatile("cp.async.wait_group 1;\n" ::: "memory");
        } else {
            asm volatile("cp.async.wait_group 0;\n" ::: "memory");
        }
        __syncthreads();

        #pragma unroll
        for (int ks = 0; ks < 4; ks++) {
            int kb = ks * 8;
            uint32_t af[4][4], bf[4][2];
            #pragma unroll
            for (int mt = 0; mt < 4; mt++) {
                int m0 = wm + mt * 16;
                af[mt][0] = AS(st, kb + tg,     m0 + g);
                af[mt][1] = AS(st, kb + tg,     m0 + g + 8);
                af[mt][2] = AS(st, kb + tg + 4, m0 + g);
                af[mt][3] = AS(st, kb + tg + 4, m0 + g + 8);
            }
            #pragma unroll
            for (int nt = 0; nt < 4; nt++) {
                int n0 = wn + nt * 8;
                bf[nt][0] = BS(st, kb + tg,     n0 + g);
                bf[nt][1] = BS(st, kb + tg + 4, n0 + g);
            }
            #pragma unroll
            for (int mt = 0; mt < 4; mt++)
                #pragma unroll
                for (int nt = 0; nt < 4; nt++)
                    mma_tf32(acc[mt][nt], af[mt][0], af[mt][1], af[mt][2], af[mt][3],
                             bf[nt][0], bf[nt][1]);
        }
        __syncthreads();
    }

    #pragma unroll
    for (int nt = 0; nt < 4; nt++) {
        int n = bn + wn + nt * 8 + 2 * tg;
        float2 sc = make_float2(1.f, 1.f);
        if (cs) sc = *(const float2*)(cs + (size_t)b * HWIMG + n);
        #pragma unroll
        for (int mt = 0; mt < 4; mt++) {
            int m0 = bm + wm + mt * 16 + g;
            int m1 = m0 + 8;
            if (m0 < M) {
                size_t off = ((size_t)b * M + m0) * HWIMG + n;
                float2 o = make_float2(acc[mt][nt][0] * sc.x, acc[mt][nt][1] * sc.y);
                if (RESID) {
                    float2 r = *(const float2*)(R + off);
                    o.x += r.x; o.y += r.y;
                }
                *(float2*)(Y + off) = o;
            }
            if (m1 < M) {
                size_t off = ((size_t)b * M + m1) * HWIMG + n;
                float2 o = make_float2(acc[mt][nt][2] * sc.x, acc[mt][nt][3] * sc.y);
                if (RESID) {
                    float2 r = *(const float2*)(R + off);
                    o.x += r.x; o.y += r.y;
                }
                *(float2*)(Y + off) = o;
            }
        }
    }
}

// ---------------- tiled depthwise 3x3 (float4 loads, pitch 76) ----------------
#define DWP 76

__device__ __forceinline__ void dw_load_tile4(const float* __restrict__ ip,
                                              float* __restrict__ tile,
                                              int y0, int x0, int tid) {
    for (int i = tid; i < 34 * 18; i += 256) {
        int r = i / 18, k = i - r * 18;
        int gy = y0 - 1 + r;
        int gx = x0 - 4 + k * 4;
        float4 v = make_float4(0.f, 0.f, 0.f, 0.f);
        if (gy >= 0 && gy < 256 && gx >= 0 && gx < 256)
            v = *(const float4*)(ip + gy * IMW + gx);
        *(float4*)&tile[r * DWP + k * 4] = v;
    }
}

__device__ __forceinline__ void dw_compute8(const float* __restrict__ tile,
                                            const float* __restrict__ wr,
                                            int row, int col0, float* o) {
    float r0[10], r1[10], r2[10];
    const float* t0 = tile + row * DWP + col0 + 3;
    #pragma unroll
    for (int j = 0; j < 10; j++) {
        r0[j] = t0[j];
        r1[j] = t0[DWP + j];
        r2[j] = t0[2 * DWP + j];
    }
    #pragma unroll
    for (int j = 0; j < 8; j++) {
        o[j] = r0[j] * wr[0] + r0[j+1] * wr[1] + r0[j+2] * wr[2]
             + r1[j] * wr[3] + r1[j+1] * wr[4] + r1[j+2] * wr[5]
             + r2[j] * wr[6] + r2[j+1] * wr[7] + r2[j+2] * wr[8];
    }
}

__global__ void __launch_bounds__(256) dwconv_kernel(
        const float* __restrict__ in, const float* __restrict__ w,
        float* __restrict__ out, int C) {
    __shared__ float tile[34 * DWP];
    int tid = threadIdx.x;
    int t   = blockIdx.x;
    int c   = blockIdx.y, b = blockIdx.z;
    int y0  = (t >> 2) * 32, x0 = (t & 3) * 64;

    const float* ip = in + ((size_t)b * C + c) * HWIMG;
    dw_load_tile4(ip, tile, y0, x0, tid);
    float wr[9];
    #pragma unroll
    for (int j = 0; j < 9; j++) wr[j] = w[c * 9 + j];
    __syncthreads();

    int row = tid >> 3, col0 = (tid & 7) * 8;
    float o[8];
    dw_compute8(tile, wr, row, col0, o);
    float* op = out + ((size_t)b * C + c) * HWIMG + (y0 + row) * IMW + x0 + col0;
    *(float4*)op       = make_float4(o[0], o[1], o[2], o[3]);
    *(float4*)(op + 4) = make_float4(o[4], o[5], o[6], o[7]);
}

__global__ void __launch_bounds__(256) dwgate_kernel(
        const float* __restrict__ in, const float* __restrict__ w,
        float* __restrict__ gout) {
    __shared__ float tile1[34 * DWP];
    __shared__ float tile2[34 * DWP];
    int tid = threadIdx.x;
    int t   = blockIdx.x;
    int c   = blockIdx.y, b = blockIdx.z;
    int y0  = (t >> 2) * 32, x0 = (t & 3) * 64;

    const float* ip1 = in + ((size_t)b * CHID2 + c) * HWIMG;
    const float* ip2 = in + ((size_t)b * CHID2 + CHID + c) * HWIMG;
    dw_load_tile4(ip1, tile1, y0, x0, tid);
    dw_load_tile4(ip2, tile2, y0, x0, tid);
    float wr1[9], wr2[9];
    #pragma unroll
    for (int j = 0; j < 9; j++) {
        wr1[j] = w[c * 9 + j];
        wr2[j] = w[(CHID + c) * 9 + j];
    }
    __syncthreads();

    int row = tid >> 3, col0 = (tid & 7) * 8;
    float v1[8], v2[8];
    dw_compute8(tile1, wr1, row, col0, v1);
    dw_compute8(tile2, wr2, row, col0, v2);
    float o[8];
    #pragma unroll
    for (int j = 0; j < 8; j++) {
        float ge = 0.5f * v1[j] * (1.f + erff(v1[j] * 0.70710678118654752f));
        o[j] = ge * v2[j];
    }
    float* op = gout + ((size_t)b * CHID + c) * HWIMG + (y0 + row) * IMW + x0 + col0;
    *(float4*)op       = make_float4(o[0], o[1], o[2], o[3]);
    *(float4*)(op + 4) = make_float4(o[4], o[5], o[6], o[7]);
}

// ---------------- windowed FFT attention: ALL contractions on tensor pipe ----------------
#define SM_DS  0
#define SM_SX  5376
#define SM_ATR 5376
#define SM_ATI 7616
#define SM_PT  9856
#define SM_QKT 15104
#define SM_VT  23168
#define SM_SC  27648
#define ATTN_SMEM_FLOATS 27688

__global__ void __launch_bounds__(256) attn_kernel(
        const float* __restrict__ qkv, const float* __restrict__ temp,
        float* __restrict__ outp) {
    extern __shared__ float sm[];
    uint32_t* Ds  = (uint32_t*)(sm + SM_DS);
    uint32_t* sx  = (uint32_t*)(sm + SM_SX);
    uint32_t* atr = (uint32_t*)(sm + SM_ATR);
    uint32_t* ati = (uint32_t*)(sm + SM_ATI);
    uint32_t* PT  = (uint32_t*)(sm + SM_PT);
    uint32_t* QKT = (uint32_t*)(sm + SM_QKT);
    uint32_t* VT  = (uint32_t*)(sm + SM_VT);
    float*    sc  = sm + SM_SC;

    int tid  = threadIdx.x;
    int warp = tid >> 5, lane = tid & 31;
    int g    = lane >> 2, tg = lane & 3;
    int wy   = blockIdx.x >> 5, wx = blockIdx.x & 31;
    int head = blockIdx.y, b = blockIdx.z;
    float tv = temp[head];

    size_t base = ((size_t)b * C6 + head * CH) * HWIMG + (size_t)(wy * 8) * IMW + wx * 8;

    for (int i = tid; i < 64 * 84; i += 256) Ds[i] = g_dft[i];
    for (int i = tid; i < 3 * CH * 64; i += 256) {
        int t = i / 3072, rem = i - t * 3072;
        int c = rem >> 6, n = rem & 63;
        float v = qkv[base + (size_t)(t * C2 + c) * HWIMG + (n >> 3) * IMW + (n & 7)];
        sx[n * 152 + t * CH + c] = f2tf(v);
    }
    __syncthreads();

    // DFT  QFT[fcomp][c] = sum_t E[fcomp][t] * X[c][t]
    for (int t8 = warp; t8 < 90; t8 += 8) {
        int mt = t8 / 18, nt = t8 % 18;
        int m0 = mt * 16, n0 = nt * 8;
        int mA = m0 + g, mB = mA + 8;
        int colA = (mA < 40) ? 2 * mA : 2 * (mA - 40) + 1;
        int colB = (mB < 40) ? 2 * mB : 2 * (mB - 40) + 1;
        float acc[4] = {0.f, 0.f, 0.f, 0.f};
        #pragma unroll
        for (int kc = 0; kc < 8; kc++) {
            int kb = kc * 8;
            uint32_t a0 = Ds[(kb + tg)     * 84 + colA];
            uint32_t a1 = Ds[(kb + tg)     * 84 + colB];
            uint32_t a2 = Ds[(kb + tg + 4) * 84 + colA];
            uint32_t a3 = Ds[(kb + tg + 4) * 84 + colB];
            uint32_t b0 = sx[(kb + tg)     * 152 + n0 + g];
            uint32_t b1 = sx[(kb + tg + 4) * 152 + n0 + g];
            mma_tf32(acc, a0, a1, a2, a3, b0, b1);
        }
        int c0 = n0 + 2 * tg;
        if (n0 < 96) {
            QKT[c0 * 84 + mA]       = f2tf(acc[0]);
            QKT[(c0 + 1) * 84 + mA] = f2tf(acc[1]);
            QKT[c0 * 84 + mB]       = f2tf(acc[2]);
            QKT[(c0 + 1) * 84 + mB] = f2tf(acc[3]);
        } else {
            int cv = c0 - 96;
            VT[mA * 56 + cv]     = f2tf(acc[0]);
            VT[mA * 56 + cv + 1] = f2tf(acc[1]);
            VT[mB * 56 + cv]     = f2tf(acc[2]);
            VT[mB * 56 + cv + 1] = f2tf(acc[3]);
        }
    }
    __syncthreads();

    // gram -> atT[g][f]
    for (int t8 = warp; t8 < 15; t8 += 8) {
        int mt = t8 / 5, nt = t8 % 5;
        int m0 = mt * 16, n0 = nt * 8;
        int fA = m0 + g, fB = fA + 8;
        int ciA = 40 + ((fA < 40) ? fA : 0);
        int ciB = 40 + ((fB < 40) ? fB : 0);
        float aR[4] = {0,0,0,0}, aI[4] = {0,0,0,0};
        #pragma unroll
        for (int kc = 0; kc < 6; kc++) {
            int kb = kc * 8;
            uint32_t qr0 = QKT[(kb + tg)     * 84 + fA];
            uint32_t qr1 = QKT[(kb + tg)     * 84 + fB];
            uint32_t qr2 = QKT[(kb + tg + 4) * 84 + fA];
            uint32_t qr3 = QKT[(kb + tg + 4) * 84 + fB];
            uint32_t qi0 = QKT[(kb + tg)     * 84 + ciA];
            uint32_t qi1 = QKT[(kb + tg)     * 84 + ciB];
            uint32_t qi2 = QKT[(kb + tg + 4) * 84 + ciA];
            uint32_t qi3 = QKT[(kb + tg + 4) * 84 + ciB];
            uint32_t kr0 = QKT[(48 + kb + tg)     * 84 + n0 + g];
            uint32_t kr1 = QKT[(48 + kb + tg + 4) * 84 + n0 + g];
            uint32_t ki0 = QKT[(48 + kb + tg)     * 84 + 40 + n0 + g];
            uint32_t ki1 = QKT[(48 + kb + tg + 4) * 84 + 40 + n0 + g];
            mma_tf32(aR, qr0, qr1, qr2, qr3, kr0, kr1);
            mma_tf32(aR, qi0, qi1, qi2, qi3, fneg(ki0), fneg(ki1));
            mma_tf32(aI, qr0, qr1, qr2, qr3, ki0, ki1);
            mma_tf32(aI, qi0, qi1, qi2, qi3, kr0, kr1);
        }
        int gc0 = n0 + 2 * tg, gc1 = gc0 + 1;
        atr[gc0 * 56 + fA] = f2tf(aR[0]);  ati[gc0 * 56 + fA] = f2tf(aI[0]);
        atr[gc1 * 56 + fA] = f2tf(aR[1]);  ati[gc1 * 56 + fA] = f2tf(aI[1]);
        atr[gc0 * 56 + fB] = f2tf(aR[2]);  ati[gc0 * 56 + fB] = f2tf(aI[2]);
        atr[gc1 * 56 + fB] = f2tf(aR[3]);  ati[gc1 * 56 + fB] = f2tf(aI[3]);
    }
    __syncthreads();

    // row norms -> scale[f]; zero PT pad rows
    if (tid < NF) {
        float s = 0.f;
        #pragma unroll 3
        for (int g2 = 0; g2 < NF; g2++) {
            float ar = __uint_as_float(atr[g2 * 56 + tid]);
            float ai = __uint_as_float(ati[g2 * 56 + tid]);
            s += ar * ar + ai * ai;
        }
        float w = (tid == 0 || tid == 32) ? 1.f : 2.f;
        sc[tid] = copysignf(1.f, tv) * rsqrtf(s) * w * (1.f / 64.f);
    }
    for (int i = tid; i < 6 * 56; i += 256) PT[66 * 56 + i] = 0u;
    __syncthreads();

    // apply -> PT[2f][c]
    for (int t8 = warp; t8 < 18; t8 += 8) {
        int mt = t8 / 6, nt = t8 % 6;
        int m0 = mt * 16, n0 = nt * 8;
        float pR[4] = {0,0,0,0}, pI[4] = {0,0,0,0};
        #pragma unroll
        for (int kc = 0; kc < 5; kc++) {
            int kb = kc * 8;
            uint32_t vr0 = VT[(kb + tg)          * 56 + m0 + g];
            uint32_t vr1 = VT[(kb + tg)          * 56 + m0 + g + 8];
            uint32_t vr2 = VT[(kb + tg + 4)      * 56 + m0 + g];
            uint32_t vr3 = VT[(kb + tg + 4)      * 56 + m0 + g + 8];
            uint32_t vi0 = VT[(40 + kb + tg)     * 56 + m0 + g];
            uint32_t vi1 = VT[(40 + kb + tg)     * 56 + m0 + g + 8];
            uint32_t vi2 = VT[(40 + kb + tg + 4) * 56 + m0 + g];
            uint32_t vi3 = VT[(40 + kb + tg + 4) * 56 + m0 + g + 8];
            uint32_t bR0 = atr[(kb + tg)     * 56 + n0 + g];
            uint32_t bR1 = atr[(kb + tg + 4) * 56 + n0 + g];
            uint32_t bI0 = ati[(kb + tg)     * 56 + n0 + g];
            uint32_t bI1 = ati[(kb + tg + 4) * 56 + n0 + g];
            mma_tf32(pR, vr0, vr1, vr2, vr3, bR0, bR1);
            mma_tf32(pR, fneg(vi0), fneg(vi1), fneg(vi2), fneg(vi3), bI0, bI1);
            mma_tf32(pI, vr0, vr1, vr2, vr3, bI0, bI1);
            mma_tf32(pI, vi0, vi1, vi2, vi3, bR0, bR1);
        }
        int c0 = m0 + g, c1 = c0 + 8;
        int f0 = n0 + 2 * tg, f1 = f0 + 1;
        if (f0 < NF) {
            float s = sc[f0];
            PT[(2 * f0) * 56 + c0]     = f2tf(pR[0] * s);
            PT[(2 * f0 + 1) * 56 + c0] = f2tf(pI[0] * s);
            PT[(2 * f0) * 56 + c1]     = f2tf(pR[2] * s);
            PT[(2 * f0 + 1) * 56 + c1] = f2tf(pI[2] * s);
        }
        if (f1 < NF) {
            float s = sc[f1];
            PT[(2 * f1) * 56 + c0]     = f2tf(pR[1] * s);
            PT[(2 * f1 + 1) * 56 + c0] = f2tf(pI[1] * s);
            PT[(2 * f1) * 56 + c1]     = f2tf(pR[3] * s);
            PT[(2 * f1 + 1) * 56 + c1] = f2tf(pI[3] * s);
        }
    }
    __syncthreads();

    // irDFT
    float* outBase = outp + ((size_t)b * C2 + head * CH) * HWIMG
                   + (size_t)(wy * 8) * IMW + wx * 8;
    for (int t8 = warp; t8 < 24; t8 += 8) {
        int mt = t8 / 8, nt = t8 % 8;
        int m0 = mt * 16, n0 = nt * 8;
        float acc[4] = {0.f, 0.f, 0.f, 0.f};
        #pragma unroll
        for (int kc = 0; kc < 9; kc++) {
            int kb = kc * 8;
            uint32_t a0 = PT[(kb + tg)     * 56 + m0 + g];
            uint32_t a1 = PT[(kb + tg)     * 56 + m0 + g + 8];
            uint32_t a2 = PT[(kb + tg + 4) * 56 + m0 + g];
            uint32_t a3 = PT[(kb + tg + 4) * 56 + m0 + g + 8];
            uint32_t b0 = Ds[(n0 + g) * 84 + kb + tg];
            uint32_t b1 = Ds[(n0 + g) * 84 + kb + tg + 4];
            mma_tf32(acc, a0, a1, a2, a3, b0, b1);
        }
        int c = m0 + g;
        *(float2*)&outBase[(size_t)c       * HWIMG + nt * IMW + 2 * tg] =
            make_float2(acc[0], acc[1]);
        *(float2*)&outBase[(size_t)(c + 8) * HWIMG + nt * IMW + 2 * tg] =
            make_float2(acc[2], acc[3]);
    }
}

// ---------------- launch ----------------
extern "C" void kernel_launch(void* const* d_in, const int* in_sizes, int n_in,
                              void* d_out, int out_size) {
    const float* x      = (const float*)d_in[0];
    const float* w_hid  = (const float*)d_in[1];
    const float* w_hdw  = (const float*)d_in[2];
    const float* w_proj = (const float*)d_in[3];
    const float* temp   = (const float*)d_in[4];
    const float* n1w    = (const float*)d_in[5];
    const float* n2w    = (const float*)d_in[6];
    const float* w_fin  = (const float*)d_in[7];
    const float* w_fdw  = (const float*)d_in[8];
    const float* w_fout = (const float*)d_in[9];
    float* out = (float*)d_out;

    float *h1, *h2, *att, *x1, *f1, *gg, *inv;
    cudaGetSymbolAddress((void**)&h1,  g_h1);
    cudaGetSymbolAddress((void**)&h2,  g_h2);
    cudaGetSymbolAddress((void**)&att, g_att);
    cudaGetSymbolAddress((void**)&x1,  g_x1);
    cudaGetSymbolAddress((void**)&f1,  g_f1);
    cudaGetSymbolAddress((void**)&gg,  g_g);
    cudaGetSymbolAddress((void**)&inv, g_inv);

    cudaFuncSetAttribute(attn_kernel, cudaFuncAttributeMaxDynamicSharedMemorySize,
                         ATTN_SMEM_FLOATS * 4);
    cudaFuncSetAttribute(gemm_tf32_kernel<false>,
                         cudaFuncAttributeMaxDynamicSharedMemorySize, GEMM_SMEM_BYTES);
    cudaFuncSetAttribute(gemm_tf32_kernel<true>,
                         cudaFuncAttributeMaxDynamicSharedMemorySize, GEMM_SMEM_BYTES);

    // 0) twiddle init
    dft_init_kernel<<<21, 256>>>();
    // 1) LN1 scale
    ln_scale_kernel<<<dim3(256, BDIM), 256>>>(x, inv);
    // 2) to_hidden 1x1 (96 -> 576), LN fused
    gemm_tf32_kernel<false><<<dim3(512, 5, BDIM), 256, GEMM_SMEM_BYTES>>>(
        w_hid, x, nullptr, n1w, inv, h1, C6, CDIM);
    // 3) dwconv 3x3 (tiled, float4)
    dwconv_kernel<<<dim3(32, C6, BDIM), 256>>>(h1, w_hdw, h2, C6);
    // 4) windowed FFT attention (full-MMA)
    attn_kernel<<<dim3(1024, HEADS, BDIM), 256, ATTN_SMEM_FLOATS * 4>>>(h2, temp, att);
    // 5) project_out 1x1 (192 -> 96) + residual x
    gemm_tf32_kernel<true><<<dim3(512, 1, BDIM), 256, GEMM_SMEM_BYTES>>>(
        w_proj, att, x, nullptr, nullptr, x1, CDIM, C2);
    // 6) LN2 scale
    ln_scale_kernel<<<dim3(256, BDIM), 256>>>(x1, inv);
    // 7) ffn in 1x1 (96 -> 510), LN fused
    gemm_tf32_kernel<false><<<dim3(512, 4, BDIM), 256, GEMM_SMEM_BYTES>>>(
        w_fin, x1, nullptr, n2w, inv, f1, CHID2, CDIM);
    // 8) fused dwconv + gelu gate
    dwgate_kernel<<<dim3(32, CHID, BDIM), 256>>>(f1, w_fdw, gg);
    // 9) ffn out 1x1 (255 -> 96) + residual x1 -> d_out
    gemm_tf32_kernel<true><<<dim3(512, 1, BDIM), 256, GEMM_SMEM_BYTES>>>(
        w_fout, gg, x1, nullptr, nullptr, out, CDIM, CHID);
}